// round 2
// baseline (speedup 1.0000x reference)
#include <cuda_runtime.h>
#include <math.h>

#define B_    2
#define T_    4096
#define DM    1024
#define DI    2048
#define CHK   256
#define NC    16
#define KSZ   5
#define NORM_EPS 1e-6f
#define DW_CAP  0.1f
#define G_CAP   0.02f
#define DEC_MIN 0.9f
#define DEC_MAX 0.995f
#define INV_C (1.0f/256.0f)

// ---------------- scratch (device globals; no allocation allowed) ----------
__device__ float  g_zu[(size_t)B_*T_*DI];          // 64 MB  rms-normed z
__device__ float  g_vu[(size_t)B_*T_*DM];          // 32 MB  double-rms-normed conv
__device__ float  g_G [(size_t)B_*NC*DM*DI];       // 256 MB G_k (already /C)
__device__ float  g_dW[(size_t)B_*NC*DM*DI];       // 256 MB dW after chunk k
__device__ double g_w0n2;
__device__ double g_gn2[B_*NC];
__device__ double g_dot[B_*NC];
__device__ double g_dwn2[B_];
__device__ float  g_coefA[B_*NC];
__device__ float  g_coefB[B_*NC];

// ---------------- init ------------------------------------------------------
__global__ void zero_scalars_k() {
    int i = threadIdx.x;
    if (i == 0) g_w0n2 = 0.0;
    if (i < B_*NC) { g_gn2[i] = 0.0; g_dot[i] = 0.0; }
    if (i < B_)    g_dwn2[i] = 0.0;
}

// ---------------- ||W0||^2 --------------------------------------------------
__global__ void w0norm_k(const float* __restrict__ W0) {
    __shared__ double sred[256];
    double s = 0.0;
    for (int i = blockIdx.x*blockDim.x + threadIdx.x; i < DM*DI; i += gridDim.x*blockDim.x) {
        float v = W0[i];
        s += (double)v * (double)v;
    }
    sred[threadIdx.x] = s; __syncthreads();
    for (int o = 128; o > 0; o >>= 1) {
        if (threadIdx.x < o) sred[threadIdx.x] += sred[threadIdx.x + o];
        __syncthreads();
    }
    if (threadIdx.x == 0) atomicAdd(&g_w0n2, sred[0]);
}

// ---------------- causal depthwise conv + double rmsnorm -> vu --------------
__global__ void conv_vu_k(const float* __restrict__ src, const float* __restrict__ cw) {
    int bt = blockIdx.x;
    int b  = bt / T_;
    int t  = bt % T_;
    float vals[4];
    float ss = 0.f;
#pragma unroll
    for (int q = 0; q < 4; q++) {
        int o = threadIdx.x + q*256;
        float acc = 0.f;
#pragma unroll
        for (int j = 0; j < KSZ; j++) {
            int tt = t - (KSZ-1) + j;
            float x = (tt >= 0) ? src[((size_t)b*T_ + tt)*DM + o] : 0.f;
            acc = fmaf(x, cw[o*KSZ + j], acc);
        }
        vals[q] = acc;
        ss += acc*acc;
    }
    __shared__ float red[256];
    red[threadIdx.x] = ss; __syncthreads();
    for (int o = 128; o > 0; o >>= 1) {
        if (threadIdx.x < o) red[threadIdx.x] += red[threadIdx.x + o];
        __syncthreads();
    }
    float ms  = red[0] * (1.0f/DM);
    float s1  = rsqrtf(ms + NORM_EPS);
    float ms2 = ms * s1 * s1;                 // mean-square after 1st norm
    float s2  = rsqrtf(ms2 + NORM_EPS);       // reference norms the chunk again
    float s   = s1 * s2;
#pragma unroll
    for (int q = 0; q < 4; q++) {
        int o = threadIdx.x + q*256;
        g_vu[(size_t)bt*DM + o] = vals[q] * s;
    }
}

// ---------------- rmsnorm(z) -> zu ------------------------------------------
__global__ void z_rms_k(const float* __restrict__ z) {
    int bt = blockIdx.x;
    const float* row = z + (size_t)bt*DI;
    float vals[8];
    float ss = 0.f;
#pragma unroll
    for (int q = 0; q < 8; q++) {
        int d = threadIdx.x + q*256;
        float v = row[d];
        vals[q] = v;
        ss += v*v;
    }
    __shared__ float red[256];
    red[threadIdx.x] = ss; __syncthreads();
    for (int o = 128; o > 0; o >>= 1) {
        if (threadIdx.x < o) red[threadIdx.x] += red[threadIdx.x + o];
        __syncthreads();
    }
    float s = rsqrtf(red[0]*(1.0f/DI) + NORM_EPS);
#pragma unroll
    for (int q = 0; q < 8; q++) {
        int d = threadIdx.x + q*256;
        g_zu[(size_t)bt*DI + d] = vals[q] * s;
    }
}

// ---------------- batched G GEMM: G[o,d] = sum_t vu[t,o] zu[t,d] / C --------
// TN layout (K=t is leading): no transpose needed into smem.
__global__ void __launch_bounds__(256, 2) gemmG_k() {
    int bk = blockIdx.z;                       // b*NC + k ; chunk base = bk*CHK
    const float* A  = g_vu + (size_t)bk*CHK*DM;   // [t][o]
    const float* Bp = g_zu + (size_t)bk*CHK*DI;   // [t][d]
    float* Cg = g_G + (size_t)bk*DM*DI;
    int obase = blockIdx.y*128;
    int dbase = blockIdx.x*128;

    __shared__ float As[16][128];
    __shared__ float Bs[16][128];
    __shared__ float red[256];

    float acc[8][8];
#pragma unroll
    for (int i = 0; i < 8; i++)
#pragma unroll
        for (int j = 0; j < 8; j++) acc[i][j] = 0.f;

    int tid = threadIdx.x;
    int tm = tid >> 4, tn = tid & 15;

    for (int k0 = 0; k0 < CHK; k0 += 16) {
#pragma unroll
        for (int i = 0; i < 2; i++) {
            int f = tid + i*256; int row = f >> 5; int c4 = f & 31;
            *(float4*)(&As[row][c4*4]) =
                *(const float4*)(A + (size_t)(k0+row)*DM + obase + c4*4);
        }
#pragma unroll
        for (int i = 0; i < 2; i++) {
            int f = tid + i*256; int row = f >> 5; int c4 = f & 31;
            *(float4*)(&Bs[row][c4*4]) =
                *(const float4*)(Bp + (size_t)(k0+row)*DI + dbase + c4*4);
        }
        __syncthreads();
#pragma unroll
        for (int kk = 0; kk < 16; kk++) {
            float a0[8], b0[8];
            *(float4*)(a0)   = *(const float4*)(&As[kk][tm*8]);
            *(float4*)(a0+4) = *(const float4*)(&As[kk][tm*8+4]);
            *(float4*)(b0)   = *(const float4*)(&Bs[kk][tn*8]);
            *(float4*)(b0+4) = *(const float4*)(&Bs[kk][tn*8+4]);
#pragma unroll
            for (int i = 0; i < 8; i++)
#pragma unroll
                for (int j = 0; j < 8; j++)
                    acc[i][j] = fmaf(a0[i], b0[j], acc[i][j]);
        }
        __syncthreads();
    }

    // epilogue: scale by 1/C, store, accumulate ||G||^2
    float ssum = 0.f;
#pragma unroll
    for (int i = 0; i < 8; i++) {
        float g[8];
#pragma unroll
        for (int j = 0; j < 8; j++) {
            g[j] = acc[i][j] * INV_C;
            ssum += g[j]*g[j];
        }
        float* rp = Cg + (size_t)(obase + tm*8 + i)*DI + dbase + tn*8;
        *(float4*)(rp)   = *(float4*)(g);
        *(float4*)(rp+4) = *(float4*)(g+4);
    }
    red[tid] = ssum; __syncthreads();
    for (int o = 128; o > 0; o >>= 1) {
        if (tid < o) red[tid] += red[tid + o];
        __syncthreads();
    }
    if (tid == 0) atomicAdd(&g_gn2[bk], (double)red[0]);
}

// ---------------- dot = <dW_{k-1}, G_k> per batch ---------------------------
__global__ void dot_k(int k) {
    int b = blockIdx.y;
    const float* dw = g_dW + (size_t)(b*NC + k - 1)*DM*DI;
    const float* G  = g_G  + (size_t)(b*NC + k    )*DM*DI;
    float s = 0.f;
    for (int i = blockIdx.x*blockDim.x + threadIdx.x; i < DM*DI; i += gridDim.x*blockDim.x)
        s = fmaf(dw[i], G[i], s);
    __shared__ float red[256];
    red[threadIdx.x] = s; __syncthreads();
    for (int o = 128; o > 0; o >>= 1) {
        if (threadIdx.x < o) red[threadIdx.x] += red[threadIdx.x + o];
        __syncthreads();
    }
    if (threadIdx.x == 0) atomicAdd(&g_dot[b*NC + k], (double)red[0]);
}

// ---------------- scalar chain for step k -----------------------------------
__global__ void scal_k(int k, const float* __restrict__ lil, const float* __restrict__ ldl) {
    if (threadIdx.x != 0) return;
    float eta   = expf(lil[0]);
    float sg    = 1.f / (1.f + expf(-ldl[0]));
    float decay = DEC_MIN + (DEC_MAX - DEC_MIN)*sg;
    float W0n   = (float)sqrt(g_w0n2);
    for (int b = 0; b < B_; b++) {
        double gn2 = g_gn2[b*NC + k];
        float  gn  = sqrtf((float)gn2);
        float  gsc = fminf(G_CAP * W0n / (gn + 1e-8f), 1.f);
        float  c   = (1.f - decay) * eta * gsc;          // dW += c * G_raw
        double dot = (k > 0) ? g_dot[b*NC + k] : 0.0;
        double in2 = (double)decay*(double)decay*g_dwn2[b]
                   + (double)c*(double)c*gn2
                   + 2.0*(double)decay*(double)c*dot;
        float n = sqrtf((float)(in2 > 0.0 ? in2 : 0.0));
        float s = fminf(DW_CAP * W0n / (n + 1e-8f), 1.f);
        g_coefA[b*NC + k] = s * decay;
        g_coefB[b*NC + k] = s * c;
        g_dwn2[b] = in2 * (double)s * (double)s;
    }
}

// ---------------- dW_k = cA*dW_{k-1} + cB*G_k (elementwise, float4) ---------
__global__ void upd_k(int k) {
    int b = blockIdx.y;
    float ca = g_coefA[b*NC + k];
    float cb = g_coefB[b*NC + k];
    float4*       dst  = (float4*)(g_dW + (size_t)(b*NC + k)*DM*DI);
    const float4* G    = (const float4*)(g_G + (size_t)(b*NC + k)*DM*DI);
    const float4* prev = (k > 0) ? (const float4*)(g_dW + (size_t)(b*NC + k - 1)*DM*DI) : nullptr;
    int n4 = DM*DI/4;
    for (int i = blockIdx.x*blockDim.x + threadIdx.x; i < n4; i += gridDim.x*blockDim.x) {
        float4 g = G[i];
        float4 r;
        if (prev) {
            float4 p = prev[i];
            r.x = fmaf(ca, p.x, cb*g.x); r.y = fmaf(ca, p.y, cb*g.y);
            r.z = fmaf(ca, p.z, cb*g.z); r.w = fmaf(ca, p.w, cb*g.w);
        } else {
            r.x = cb*g.x; r.y = cb*g.y; r.z = cb*g.z; r.w = cb*g.w;
        }
        dst[i] = r;
    }
}

// ---------------- batched out GEMM: out[t,o] = z[t,:]·(W0+dW_{k-1})[o,:] + bias
// NT layout: both operands K(=d)-contiguous -> transpose into smem.
__global__ void __launch_bounds__(256, 2) gemmOut_k(const float* __restrict__ z,
                                                    const float* __restrict__ W0,
                                                    const float* __restrict__ bias,
                                                    float* __restrict__ out) {
    int bk = blockIdx.z;
    int k  = bk & (NC-1);
    const float* A   = z + (size_t)bk*CHK*DI;                          // [t][d]
    const float* dWp = (k > 0) ? (g_dW + (size_t)(bk - 1)*DM*DI) : nullptr;
    float* Cout = out + (size_t)bk*CHK*DM;
    int tbase = blockIdx.y*128;
    int obase = blockIdx.x*128;

    __shared__ float As[16][128];
    __shared__ float Bs[16][128];

    float acc[8][8];
#pragma unroll
    for (int i = 0; i < 8; i++)
#pragma unroll
        for (int j = 0; j < 8; j++) acc[i][j] = 0.f;

    int tid = threadIdx.x;
    int tm = tid >> 4, tn = tid & 15;

    for (int k0 = 0; k0 < DI; k0 += 16) {
#pragma unroll
        for (int i = 0; i < 2; i++) {
            int f = tid + i*256; int row = f >> 2; int c4 = f & 3;
            float4 v = *(const float4*)(A + (size_t)(tbase+row)*DI + k0 + c4*4);
            As[c4*4+0][row] = v.x; As[c4*4+1][row] = v.y;
            As[c4*4+2][row] = v.z; As[c4*4+3][row] = v.w;
        }
#pragma unroll
        for (int i = 0; i < 2; i++) {
            int f = tid + i*256; int row = f >> 2; int c4 = f & 3;
            size_t off = (size_t)(obase+row)*DI + k0 + c4*4;
            float4 v = *(const float4*)(W0 + off);
            if (dWp) {
                float4 u = *(const float4*)(dWp + off);
                v.x += u.x; v.y += u.y; v.z += u.z; v.w += u.w;
            }
            Bs[c4*4+0][row] = v.x; Bs[c4*4+1][row] = v.y;
            Bs[c4*4+2][row] = v.z; Bs[c4*4+3][row] = v.w;
        }
        __syncthreads();
#pragma unroll
        for (int kk = 0; kk < 16; kk++) {
            float a0[8], b0[8];
            *(float4*)(a0)   = *(const float4*)(&As[kk][tm*8]);
            *(float4*)(a0+4) = *(const float4*)(&As[kk][tm*8+4]);
            *(float4*)(b0)   = *(const float4*)(&Bs[kk][tn*8]);
            *(float4*)(b0+4) = *(const float4*)(&Bs[kk][tn*8+4]);
#pragma unroll
            for (int i = 0; i < 8; i++)
#pragma unroll
                for (int j = 0; j < 8; j++)
                    acc[i][j] = fmaf(a0[i], b0[j], acc[i][j]);
        }
        __syncthreads();
    }

#pragma unroll
    for (int i = 0; i < 8; i++) {
        float v[8];
#pragma unroll
        for (int j = 0; j < 8; j++) v[j] = acc[i][j] + bias[obase + tn*8 + j];
        float* rp = Cout + (size_t)(tbase + tm*8 + i)*DM + obase + tn*8;
        *(float4*)(rp)   = *(float4*)(v);
        *(float4*)(rp+4) = *(float4*)(v+4);
    }
}

// ---------------- final deltaW copy -----------------------------------------
__global__ void copydw_k(float* __restrict__ out) {
    const int per = DM*DI;
    for (int i = blockIdx.x*blockDim.x + threadIdx.x; i < B_*per; i += gridDim.x*blockDim.x) {
        int b = i / per;
        int r = i - b*per;
        out[i] = g_dW[(size_t)(b*NC + (NC-1))*per + r];
    }
}

// ---------------- launch -----------------------------------------------------
extern "C" void kernel_launch(void* const* d_in, const int* in_sizes, int n_in,
                              void* d_out, int out_size) {
    const float* z    = (const float*)d_in[0];
    const float* src  = (const float*)d_in[1];
    const float* W0   = (const float*)d_in[2];
    const float* bias = (const float*)d_in[3];
    const float* cw   = (const float*)d_in[4];
    const float* lil  = (const float*)d_in[5];
    const float* ldl  = (const float*)d_in[6];
    float* out = (float*)d_out;

    zero_scalars_k<<<1, 64>>>();
    w0norm_k<<<256, 256>>>(W0);
    conv_vu_k<<<B_*T_, 256>>>(src, cw);
    z_rms_k<<<B_*T_, 256>>>(z);

    gemmG_k<<<dim3(DI/128, DM/128, B_*NC), 256>>>();

    for (int k = 0; k < NC; k++) {
        if (k > 0) dot_k<<<dim3(1024, B_), 256>>>(k);
        scal_k<<<1, 32>>>(k, lil, ldl);
        upd_k<<<dim3(2048, B_), 256>>>(k);
    }

    gemmOut_k<<<dim3(DM/128, CHK/128, B_*NC), 256>>>(z, W0, bias, out);
    copydw_k<<<2048, 256>>>(out + (size_t)B_*T_*DM);
}

// round 7
// speedup vs baseline: 1.7296x; 1.7296x over previous
#include <cuda_runtime.h>
#include <cuda_bf16.h>
#include <stdint.h>
#include <math.h>

#define B_    2
#define T_    4096
#define DM    1024
#define DI    2048
#define CHK   256
#define NC    16
#define KSZ   5
#define NE    (DM*DI)
#define NPAIR 136
#define NORM_EPS 1e-6f
#define INV_C (1.0f/256.0f)

// ---------------- scratch (device globals; no allocation allowed) ----------
__device__ float          g_vu [(size_t)B_*T_*DM];     // conv+double-rms, fp32
__device__ float          g_zu [(size_t)B_*T_*DI];     // rms(z), fp32
__device__ float          g_G  [(size_t)B_*NC*NE];     // G_k (scaled by 1/C), fp32
__device__ __nv_bfloat16  g_vuT_h[(size_t)B_*DM*T_];   // vu^T hi  [b][o][t]
__device__ __nv_bfloat16  g_vuT_l[(size_t)B_*DM*T_];
__device__ __nv_bfloat16  g_zuT_h[(size_t)B_*DI*T_];   // zu^T hi  [b][d][t]
__device__ __nv_bfloat16  g_zuT_l[(size_t)B_*DI*T_];
__device__ __nv_bfloat16  g_zh [(size_t)B_*T_*DI];     // z split  [b][t][d]
__device__ __nv_bfloat16  g_zl [(size_t)B_*T_*DI];
__device__ __nv_bfloat16  g_Wh [(size_t)B_*NC*NE];     // (W0+dW_{k-1}) hi [b][k][o][d]
__device__ __nv_bfloat16  g_Wl [(size_t)B_*NC*NE];
__device__ double         g_gram[B_*NPAIR];
__device__ double         g_w0n2;
__device__ float          g_sA[B_*NC];
__device__ float          g_sB[B_*NC];

// ---------------- mma.sync / cp.async helpers (sm_80+, NOT arch-'a') -------
__device__ __forceinline__ uint32_t smem_u32(const void* p) {
    uint32_t a;
    asm("{ .reg .u64 t; cvta.to.shared.u64 t, %1; cvt.u32.u64 %0, t; }"
        : "=r"(a) : "l"(p));
    return a;
}
__device__ __forceinline__ void ldmx4(uint32_t r[4], uint32_t addr) {
    asm volatile("ldmatrix.sync.aligned.m8n8.x4.shared.b16 {%0,%1,%2,%3}, [%4];"
        : "=r"(r[0]), "=r"(r[1]), "=r"(r[2]), "=r"(r[3]) : "r"(addr));
}
__device__ __forceinline__ void mma16816(float c[4], const uint32_t a[4],
                                         uint32_t b0, uint32_t b1) {
    asm volatile("mma.sync.aligned.m16n8k16.row.col.f32.bf16.bf16.f32 "
        "{%0,%1,%2,%3}, {%4,%5,%6,%7}, {%8,%9}, {%0,%1,%2,%3};"
        : "+f"(c[0]), "+f"(c[1]), "+f"(c[2]), "+f"(c[3])
        : "r"(a[0]), "r"(a[1]), "r"(a[2]), "r"(a[3]), "r"(b0), "r"(b1));
}
#define CPASYNC16(dst, src) \
    asm volatile("cp.async.cg.shared.global [%0], [%1], 16;" :: "r"(dst), "l"(src))
#define CPCOMMIT() asm volatile("cp.async.commit_group;")
#define CPWAIT(n)  asm volatile("cp.async.wait_group %0;" :: "n"(n))

// smem: 4 operand tiles (Ah,Al,Bh,Bl), each 128 rows x 32 bf16, row stride 80B
#define SROW   80
#define TILEB  (128*SROW)     // 10240
#define BUFB   (4*TILEB)      // 40960
#define SMEM_DYN (2*BUFB)     // 81920

// ---------------- shared GEMM mainloop (128x128 tile, BK=32, 3-term split) --
__device__ __forceinline__ void gemm_mainloop(
    const __nv_bfloat16* __restrict__ Ah, const __nv_bfloat16* __restrict__ Al, int lda,
    const __nv_bfloat16* __restrict__ Bh, const __nv_bfloat16* __restrict__ Bl, int ldb,
    int K, uint32_t smb, float acc[4][4][4])
{
    int tid = threadIdx.x, lane = tid & 31, wid = tid >> 5;
    int warpM = wid >> 2, warpN = wid & 3;
    const int S = K / 32;

    int q0r = tid >> 2,          q0c = tid & 3;
    int q1r = (tid + 256) >> 2,  q1c = tid & 3;

    uint32_t aoff[4], boff[2];
#pragma unroll
    for (int mi = 0; mi < 4; mi++)
        aoff[mi] = (uint32_t)(warpM*64 + mi*16 + (lane & 15))*SROW + ((lane >> 4) & 1)*16;
#pragma unroll
    for (int bg = 0; bg < 2; bg++)
        boff[bg] = (uint32_t)(warpN*32 + bg*16 + (lane & 7) + ((lane & 16) ? 8 : 0))*SROW
                 + ((lane >> 3) & 1)*16;

    auto load_tile = [&](int s, int buf) {
        int k0 = s*32;
        uint32_t bb = smb + buf*BUFB;
        CPASYNC16(bb +            q0r*SROW + q0c*16, Ah + (size_t)q0r*lda + k0 + q0c*8);
        CPASYNC16(bb +            q1r*SROW + q1c*16, Ah + (size_t)q1r*lda + k0 + q1c*8);
        CPASYNC16(bb +   TILEB +  q0r*SROW + q0c*16, Al + (size_t)q0r*lda + k0 + q0c*8);
        CPASYNC16(bb +   TILEB +  q1r*SROW + q1c*16, Al + (size_t)q1r*lda + k0 + q1c*8);
        CPASYNC16(bb + 2*TILEB +  q0r*SROW + q0c*16, Bh + (size_t)q0r*ldb + k0 + q0c*8);
        CPASYNC16(bb + 2*TILEB +  q1r*SROW + q1c*16, Bh + (size_t)q1r*ldb + k0 + q1c*8);
        CPASYNC16(bb + 3*TILEB +  q0r*SROW + q0c*16, Bl + (size_t)q0r*ldb + k0 + q0c*8);
        CPASYNC16(bb + 3*TILEB +  q1r*SROW + q1c*16, Bl + (size_t)q1r*ldb + k0 + q1c*8);
        CPCOMMIT();
    };

    load_tile(0, 0);

    for (int s = 0; s < S; s++) {
        if (s + 1 < S) { load_tile(s + 1, (s + 1) & 1); CPWAIT(1); }
        else           { CPWAIT(0); }
        __syncthreads();
        uint32_t bb = smb + (s & 1)*BUFB;
#pragma unroll
        for (int kk = 0; kk < 2; kk++) {
            uint32_t ah[4][4], al[4][4], bh[2][4], bl[2][4];
            uint32_t kb = kk*32;
#pragma unroll
            for (int mi = 0; mi < 4; mi++) {
                ldmx4(ah[mi], bb +         aoff[mi] + kb);
                ldmx4(al[mi], bb + TILEB + aoff[mi] + kb);
            }
#pragma unroll
            for (int bg = 0; bg < 2; bg++) {
                ldmx4(bh[bg], bb + 2*TILEB + boff[bg] + kb);
                ldmx4(bl[bg], bb + 3*TILEB + boff[bg] + kb);
            }
#pragma unroll
            for (int mi = 0; mi < 4; mi++)
#pragma unroll
                for (int ni = 0; ni < 4; ni++) {
                    int bg = ni >> 1, sub = (ni & 1)*2;
                    mma16816(acc[mi][ni], ah[mi], bh[bg][sub], bh[bg][sub+1]);
                    mma16816(acc[mi][ni], ah[mi], bl[bg][sub], bl[bg][sub+1]);
                    mma16816(acc[mi][ni], al[mi], bh[bg][sub], bh[bg][sub+1]);
                }
        }
        __syncthreads();
    }
}

// ---------------- init ------------------------------------------------------
__global__ void zero_scalars_k() {
    int i = blockIdx.x*blockDim.x + threadIdx.x;
    if (i == 0) g_w0n2 = 0.0;
    if (i < B_*NPAIR) g_gram[i] = 0.0;
}

// ---------------- ||W0||^2 --------------------------------------------------
__global__ void w0norm_k(const float* __restrict__ W0) {
    __shared__ double sred[256];
    double s = 0.0;
    for (int i = blockIdx.x*blockDim.x + threadIdx.x; i < NE; i += gridDim.x*blockDim.x) {
        float v = W0[i];
        s += (double)v * (double)v;
    }
    sred[threadIdx.x] = s; __syncthreads();
    for (int o = 128; o > 0; o >>= 1) {
        if (threadIdx.x < o) sred[threadIdx.x] += sred[threadIdx.x + o];
        __syncthreads();
    }
    if (threadIdx.x == 0) atomicAdd(&g_w0n2, sred[0]);
}

// ---------------- causal depthwise conv + double rmsnorm -> vu (fp32) -------
__global__ void conv_vu_k(const float* __restrict__ src, const float* __restrict__ cw) {
    int bt = blockIdx.x;
    int b  = bt / T_;
    int t  = bt % T_;
    float vals[4];
    float ss = 0.f;
#pragma unroll
    for (int q = 0; q < 4; q++) {
        int o = threadIdx.x + q*256;
        float acc = 0.f;
#pragma unroll
        for (int j = 0; j < KSZ; j++) {
            int tt = t - (KSZ-1) + j;
            float x = (tt >= 0) ? src[((size_t)b*T_ + tt)*DM + o] : 0.f;
            acc = fmaf(x, cw[o*KSZ + j], acc);
        }
        vals[q] = acc;
        ss += acc*acc;
    }
    __shared__ float red[256];
    red[threadIdx.x] = ss; __syncthreads();
    for (int o = 128; o > 0; o >>= 1) {
        if (threadIdx.x < o) red[threadIdx.x] += red[threadIdx.x + o];
        __syncthreads();
    }
    float ms  = red[0] * (1.0f/DM);
    float s1  = rsqrtf(ms + NORM_EPS);
    float ms2 = ms * s1 * s1;
    float s2  = rsqrtf(ms2 + NORM_EPS);
    float s   = s1 * s2;
#pragma unroll
    for (int q = 0; q < 4; q++) {
        int o = threadIdx.x + q*256;
        g_vu[(size_t)bt*DM + o] = vals[q] * s;
    }
}

// ---------------- rmsnorm(z) -> zu (fp32) -----------------------------------
__global__ void z_rms_k(const float* __restrict__ z) {
    int bt = blockIdx.x;
    const float* row = z + (size_t)bt*DI;
    float vals[8];
    float ss = 0.f;
#pragma unroll
    for (int q = 0; q < 8; q++) {
        int d = threadIdx.x + q*256;
        float v = row[d];
        vals[q] = v;
        ss += v*v;
    }
    __shared__ float red[256];
    red[threadIdx.x] = ss; __syncthreads();
    for (int o = 128; o > 0; o >>= 1) {
        if (threadIdx.x < o) red[threadIdx.x] += red[threadIdx.x + o];
        __syncthreads();
    }
    float s = rsqrtf(red[0]*(1.0f/DI) + NORM_EPS);
#pragma unroll
    for (int q = 0; q < 8; q++) {
        int d = threadIdx.x + q*256;
        g_zu[(size_t)bt*DI + d] = vals[q] * s;
    }
}

// ---------------- split z -> zh/zl (K-major already) ------------------------
__global__ void zsplit_k(const float* __restrict__ z) {
    for (size_t i = (size_t)blockIdx.x*blockDim.x + threadIdx.x;
         i < (size_t)B_*T_*DI; i += (size_t)gridDim.x*blockDim.x) {
        float v = z[i];
        __nv_bfloat16 h = __float2bfloat16(v);
        __nv_bfloat16 l = __float2bfloat16(v - __bfloat162float(h));
        g_zh[i] = h; g_zl[i] = l;
    }
}

// ---------------- transpose + split [b][t][W] -> [b][W][t] bf16 hi/lo -------
// NOTE: device globals referenced in DEVICE code (host-side symbol args are
// invalid — on GB300/ATS they silently alias the zero host shadow).
__device__ __forceinline__ void tsplit_body(const float* __restrict__ src,
                                            __nv_bfloat16* __restrict__ dh,
                                            __nv_bfloat16* __restrict__ dl, int W) {
    __shared__ float tile[32][33];
    int b  = blockIdx.z;
    int w0 = blockIdx.x*32, t0 = blockIdx.y*32;
    int tid = threadIdx.x;
#pragma unroll
    for (int i = 0; i < 4; i++) {
        int q = tid + i*256; int r = q>>5, c = q&31;
        tile[r][c] = src[((size_t)b*T_ + t0 + r)*W + w0 + c];
    }
    __syncthreads();
#pragma unroll
    for (int i = 0; i < 4; i++) {
        int q = tid + i*256; int c = q>>5, r = q&31;
        float v = tile[r][c];
        __nv_bfloat16 h = __float2bfloat16(v);
        __nv_bfloat16 l = __float2bfloat16(v - __bfloat162float(h));
        size_t o = ((size_t)b*W + w0 + c)*T_ + t0 + r;
        dh[o] = h; dl[o] = l;
    }
}
__global__ void tsplit_vu_k() { tsplit_body(g_vu, g_vuT_h, g_vuT_l, DM); }
__global__ void tsplit_zu_k() { tsplit_body(g_zu, g_zuT_h, g_zuT_l, DI); }

// ---------------- HMMA GEMM: G[o,d] = sum_t vu[t,o] zu[t,d] / C -------------
__global__ void __launch_bounds__(256, 1) gemmG_hmma() {
    extern __shared__ char dsm[];
    uint32_t smb = smem_u32(dsm);
    int bk = blockIdx.z;
    int b = bk >> 4, kc = bk & 15;
    int obase = blockIdx.y*128;
    int dbase = blockIdx.x*128;
    size_t abase = ((size_t)b*DM + obase)*T_ + (size_t)kc*CHK;
    size_t bbase = ((size_t)b*DI + dbase)*T_ + (size_t)kc*CHK;

    float acc[4][4][4];
#pragma unroll
    for (int i = 0; i < 4; i++)
#pragma unroll
        for (int j = 0; j < 4; j++)
#pragma unroll
            for (int r = 0; r < 4; r++) acc[i][j][r] = 0.f;

    gemm_mainloop(g_vuT_h + abase, g_vuT_l + abase, T_,
                  g_zuT_h + bbase, g_zuT_l + bbase, T_, CHK, smb, acc);

    int lane = threadIdx.x & 31, wid = threadIdx.x >> 5;
    int warpM = wid >> 2, warpN = wid & 3;
    int g = lane >> 2, tc = (lane & 3)*2;
    float* Cg = g_G + (size_t)bk*NE;
#pragma unroll
    for (int mi = 0; mi < 4; mi++)
#pragma unroll
        for (int ni = 0; ni < 4; ni++) {
            int r0  = obase + warpM*64 + mi*16 + g;
            int col = dbase + warpN*32 + ni*8 + tc;
            float2 v0 = make_float2(acc[mi][ni][0]*INV_C, acc[mi][ni][1]*INV_C);
            float2 v1 = make_float2(acc[mi][ni][2]*INV_C, acc[mi][ni][3]*INV_C);
            *(float2*)(Cg + (size_t)r0*DI + col)     = v0;
            *(float2*)(Cg + (size_t)(r0+8)*DI + col) = v1;
        }
}

// ---------------- Gram matrix: all 136 pairwise <G_i, G_j> per batch --------
__global__ void __launch_bounds__(128, 1) gram_k() {
    int b = blockIdx.y;
    const float* Gb = g_G + (size_t)b*NC*NE;
    float acc[NPAIR];
#pragma unroll
    for (int p = 0; p < NPAIR; p++) acc[p] = 0.f;

    for (int e = blockIdx.x*128 + threadIdx.x; e < NE; e += gridDim.x*128) {
        float g[NC];
#pragma unroll
        for (int j = 0; j < NC; j++) g[j] = Gb[(size_t)j*NE + e];
        int p = 0;
#pragma unroll
        for (int j = 0; j < NC; j++)
#pragma unroll
            for (int i = 0; i <= j; i++) { acc[p] = fmaf(g[i], g[j], acc[p]); p++; }
    }
    __shared__ float sw[NPAIR*4];
    int lane = threadIdx.x & 31, w = threadIdx.x >> 5;
#pragma unroll
    for (int p = 0; p < NPAIR; p++) {
        float v = acc[p];
        v += __shfl_xor_sync(0xFFFFFFFFu, v, 16);
        v += __shfl_xor_sync(0xFFFFFFFFu, v, 8);
        v += __shfl_xor_sync(0xFFFFFFFFu, v, 4);
        v += __shfl_xor_sync(0xFFFFFFFFu, v, 2);
        v += __shfl_xor_sync(0xFFFFFFFFu, v, 1);
        if (lane == 0) sw[p*4 + w] = v;
    }
    __syncthreads();
    for (int p = threadIdx.x; p < NPAIR; p += 128)
        atomicAdd(&g_gram[b*NPAIR + p],
                  (double)(sw[p*4] + sw[p*4+1] + sw[p*4+2] + sw[p*4+3]));
}

// ---------------- scalar recursion: sA_k, sB_k from Gram --------------------
__global__ void scal2_k(const float* __restrict__ lil, const float* __restrict__ ldl) {
    int b = threadIdx.x;
    if (b >= B_) return;
    double eta   = exp((double)lil[0]);
    double sg    = 1.0/(1.0 + exp(-(double)ldl[0]));
    double decay = 0.9 + (0.995 - 0.9)*sg;
    double W0n   = sqrt(g_w0n2);
    const double* Gm = g_gram + b*NPAIR;
    double beta[NC];
#pragma unroll
    for (int j = 0; j < NC; j++) beta[j] = 0.0;
    double dwn2 = 0.0;
    for (int k = 0; k < NC; k++) {
        int rb = k*(k+1)/2;
        double gn2 = Gm[rb + k];
        double gsc = fmin(0.02*W0n/(sqrt(gn2) + 1e-8), 1.0);
        double c   = (1.0 - decay)*eta*gsc;
        double dot = 0.0;
        for (int j = 0; j < k; j++) dot += beta[j]*Gm[rb + j];
        double in2 = decay*decay*dwn2 + c*c*gn2 + 2.0*decay*c*dot;
        double s   = fmin(0.1*W0n/(sqrt(in2) + 1e-8), 1.0);
        g_sA[b*NC + k] = (float)(s*decay);
        g_sB[b*NC + k] = (float)(s*c);
        for (int j = 0; j < k; j++) beta[j] *= s*decay;
        beta[k] = s*c;
        dwn2 = in2*s*s;
    }
}

// ---------------- materialize W_k = W0 + dW_{k-1} (bf16 split) + deltaW -----
__global__ void matW_k(const float* __restrict__ W0, float* __restrict__ outDW) {
    int b = blockIdx.y;
    __shared__ float sA[NC], sB[NC];
    if (threadIdx.x < NC) { sA[threadIdx.x] = g_sA[b*NC + threadIdx.x];
                            sB[threadIdx.x] = g_sB[b*NC + threadIdx.x]; }
    __syncthreads();
    for (int e = blockIdx.x*blockDim.x + threadIdx.x; e < NE; e += gridDim.x*blockDim.x) {
        float w0 = W0[e];
        float dw = 0.f;
#pragma unroll
        for (int k = 0; k < NC; k++) {
            float w = w0 + dw;
            __nv_bfloat16 h = __float2bfloat16(w);
            __nv_bfloat16 l = __float2bfloat16(w - __bfloat162float(h));
            size_t o = ((size_t)b*NC + k)*NE + e;
            g_Wh[o] = h; g_Wl[o] = l;
            float g = g_G[((size_t)b*NC + k)*NE + e];
            dw = fmaf(sA[k], dw, sB[k]*g);
        }
        outDW[(size_t)b*NE + e] = dw;
    }
}

// ---------------- HMMA GEMM: out[t,o] = z[t,:]·W_k[o,:] + bias --------------
__global__ void __launch_bounds__(256, 1) gemmOut_hmma(const float* __restrict__ bias,
                                                       float* __restrict__ out) {
    extern __shared__ char dsm[];
    uint32_t smb = smem_u32(dsm);
    int bk = blockIdx.z;
    int obase = blockIdx.x*128;
    int tbase = blockIdx.y*128;
    size_t abase = ((size_t)bk*CHK + tbase)*DI;
    size_t bbase = (size_t)bk*NE + (size_t)obase*DI;

    float acc[4][4][4];
#pragma unroll
    for (int i = 0; i < 4; i++)
#pragma unroll
        for (int j = 0; j < 4; j++)
#pragma unroll
            for (int r = 0; r < 4; r++) acc[i][j][r] = 0.f;

    gemm_mainloop(g_zh + abase, g_zl + abase, DI,
                  g_Wh + bbase, g_Wl + bbase, DI, DI, smb, acc);

    int lane = threadIdx.x & 31, wid = threadIdx.x >> 5;
    int warpM = wid >> 2, warpN = wid & 3;
    int g = lane >> 2, tc = (lane & 3)*2;
#pragma unroll
    for (int mi = 0; mi < 4; mi++)
#pragma unroll
        for (int ni = 0; ni < 4; ni++) {
            int r0  = tbase + warpM*64 + mi*16 + g;
            int col = obase + warpN*32 + ni*8 + tc;
            float b0 = bias[col], b1 = bias[col+1];
            float2 v0 = make_float2(acc[mi][ni][0] + b0, acc[mi][ni][1] + b1);
            float2 v1 = make_float2(acc[mi][ni][2] + b0, acc[mi][ni][3] + b1);
            *(float2*)(out + ((size_t)bk*CHK + r0)*DM + col)     = v0;
            *(float2*)(out + ((size_t)bk*CHK + r0 + 8)*DM + col) = v1;
        }
}

// ---------------- launch -----------------------------------------------------
extern "C" void kernel_launch(void* const* d_in, const int* in_sizes, int n_in,
                              void* d_out, int out_size) {
    const float* z    = (const float*)d_in[0];
    const float* src  = (const float*)d_in[1];
    const float* W0   = (const float*)d_in[2];
    const float* bias = (const float*)d_in[3];
    const float* cw   = (const float*)d_in[4];
    const float* lil  = (const float*)d_in[5];
    const float* ldl  = (const float*)d_in[6];
    float* out = (float*)d_out;

    cudaFuncSetAttribute(gemmG_hmma,   cudaFuncAttributeMaxDynamicSharedMemorySize, SMEM_DYN);
    cudaFuncSetAttribute(gemmOut_hmma, cudaFuncAttributeMaxDynamicSharedMemorySize, SMEM_DYN);

    zero_scalars_k<<<2, 256>>>();
    w0norm_k<<<256, 256>>>(W0);
    conv_vu_k<<<B_*T_, 256>>>(src, cw);
    z_rms_k<<<B_*T_, 256>>>(z);
    zsplit_k<<<4096, 256>>>(z);
    tsplit_vu_k<<<dim3(DM/32, T_/32, B_), 256>>>();
    tsplit_zu_k<<<dim3(DI/32, T_/32, B_), 256>>>();

    gemmG_hmma<<<dim3(DI/128, DM/128, B_*NC), 256, SMEM_DYN>>>();

    gram_k<<<dim3(512, B_), 128>>>();
    scal2_k<<<1, 32>>>(lil, ldl);
    matW_k<<<dim3(1024, B_), 256>>>(W0, out + (size_t)B_*T_*DM);

    gemmOut_hmma<<<dim3(DM/128, CHK/128, B_*NC), 256, SMEM_DYN>>>(bias, out);
}

// round 8
// speedup vs baseline: 1.7768x; 1.0273x over previous
#include <cuda_runtime.h>
#include <cuda_bf16.h>
#include <stdint.h>
#include <math.h>

#define B_    2
#define T_    4096
#define DM    1024
#define DI    2048
#define CHK   256
#define NC    16
#define KSZ   5
#define NE    (DM*DI)
#define NPAIR 136
#define NORM_EPS 1e-6f
#define INV_C (1.0f/256.0f)

// ---------------- scratch (device globals; no allocation allowed) ----------
__device__ float          g_vu [(size_t)B_*T_*DM];     // conv+double-rms, fp32
__device__ float          g_zu [(size_t)B_*T_*DI];     // rms(z), fp32
__device__ float          g_G  [(size_t)B_*NC*NE];     // G_k (scaled by 1/C), fp32
__device__ float          g_part[(size_t)B_*T_*DM];    // split-K partial for out
__device__ __nv_bfloat16  g_vuT_h[(size_t)B_*DM*T_];   // vu^T hi  [b][o][t]
__device__ __nv_bfloat16  g_vuT_l[(size_t)B_*DM*T_];
__device__ __nv_bfloat16  g_zuT_h[(size_t)B_*DI*T_];   // zu^T hi  [b][d][t]
__device__ __nv_bfloat16  g_zuT_l[(size_t)B_*DI*T_];
__device__ __nv_bfloat16  g_zh [(size_t)B_*T_*DI];     // z split  [b][t][d]
__device__ __nv_bfloat16  g_zl [(size_t)B_*T_*DI];
__device__ __nv_bfloat16  g_Wh [(size_t)B_*NC*NE];     // (W0+dW_{k-1}) hi [b][k][o][d]
__device__ __nv_bfloat16  g_Wl [(size_t)B_*NC*NE];
__device__ double         g_gram[B_*NPAIR];
__device__ double         g_w0n2;
__device__ float          g_sA[B_*NC];
__device__ float          g_sB[B_*NC];

// ---------------- mma.sync / cp.async helpers (sm_80+, NOT arch-'a') -------
__device__ __forceinline__ uint32_t smem_u32(const void* p) {
    uint32_t a;
    asm("{ .reg .u64 t; cvta.to.shared.u64 t, %1; cvt.u32.u64 %0, t; }"
        : "=r"(a) : "l"(p));
    return a;
}
__device__ __forceinline__ void ldmx4(uint32_t r[4], uint32_t addr) {
    asm volatile("ldmatrix.sync.aligned.m8n8.x4.shared.b16 {%0,%1,%2,%3}, [%4];"
        : "=r"(r[0]), "=r"(r[1]), "=r"(r[2]), "=r"(r[3]) : "r"(addr));
}
__device__ __forceinline__ void mma16816(float c[4], const uint32_t a[4],
                                         uint32_t b0, uint32_t b1) {
    asm volatile("mma.sync.aligned.m16n8k16.row.col.f32.bf16.bf16.f32 "
        "{%0,%1,%2,%3}, {%4,%5,%6,%7}, {%8,%9}, {%0,%1,%2,%3};"
        : "+f"(c[0]), "+f"(c[1]), "+f"(c[2]), "+f"(c[3])
        : "r"(a[0]), "r"(a[1]), "r"(a[2]), "r"(a[3]), "r"(b0), "r"(b1));
}
#define CPASYNC16(dst, src) \
    asm volatile("cp.async.cg.shared.global [%0], [%1], 16;" :: "r"(dst), "l"(src))
#define CPCOMMIT() asm volatile("cp.async.commit_group;")
#define CPWAIT(n)  asm volatile("cp.async.wait_group %0;" :: "n"(n))

// smem: 4 operand tiles (Ah,Al,Bh,Bl), each 128 rows x 32 bf16, row stride 80B
#define SROW   80
#define TILEB  (128*SROW)     // 10240
#define BUFB   (4*TILEB)      // 40960
#define SMEM_DYN (3*BUFB)     // 122880 (3-stage pipeline)

// ---------------- shared GEMM mainloop (128x128 tile, BK=32, 3-term split,
//                  3-stage cp.async pipeline) -------------------------------
__device__ __forceinline__ void gemm_mainloop(
    const __nv_bfloat16* __restrict__ Ah, const __nv_bfloat16* __restrict__ Al, int lda,
    const __nv_bfloat16* __restrict__ Bh, const __nv_bfloat16* __restrict__ Bl, int ldb,
    int K, uint32_t smb, float acc[4][4][4])
{
    int tid = threadIdx.x, lane = tid & 31, wid = tid >> 5;
    int warpM = wid >> 2, warpN = wid & 3;
    const int S = K / 32;

    int q0r = tid >> 2,          q0c = tid & 3;
    int q1r = (tid + 256) >> 2,  q1c = tid & 3;

    uint32_t aoff[4], boff[2];
#pragma unroll
    for (int mi = 0; mi < 4; mi++)
        aoff[mi] = (uint32_t)(warpM*64 + mi*16 + (lane & 15))*SROW + ((lane >> 4) & 1)*16;
#pragma unroll
    for (int bg = 0; bg < 2; bg++)
        boff[bg] = (uint32_t)(warpN*32 + bg*16 + (lane & 7) + ((lane & 16) ? 8 : 0))*SROW
                 + ((lane >> 3) & 1)*16;

    auto load_tile = [&](int s, int buf) {
        int k0 = s*32;
        uint32_t bb = smb + buf*BUFB;
        CPASYNC16(bb +            q0r*SROW + q0c*16, Ah + (size_t)q0r*lda + k0 + q0c*8);
        CPASYNC16(bb +            q1r*SROW + q1c*16, Ah + (size_t)q1r*lda + k0 + q1c*8);
        CPASYNC16(bb +   TILEB +  q0r*SROW + q0c*16, Al + (size_t)q0r*lda + k0 + q0c*8);
        CPASYNC16(bb +   TILEB +  q1r*SROW + q1c*16, Al + (size_t)q1r*lda + k0 + q1c*8);
        CPASYNC16(bb + 2*TILEB +  q0r*SROW + q0c*16, Bh + (size_t)q0r*ldb + k0 + q0c*8);
        CPASYNC16(bb + 2*TILEB +  q1r*SROW + q1c*16, Bh + (size_t)q1r*ldb + k0 + q1c*8);
        CPASYNC16(bb + 3*TILEB +  q0r*SROW + q0c*16, Bl + (size_t)q0r*ldb + k0 + q0c*8);
        CPASYNC16(bb + 3*TILEB +  q1r*SROW + q1c*16, Bl + (size_t)q1r*ldb + k0 + q1c*8);
        CPCOMMIT();
    };

    // 3-stage prologue: two groups in flight
    load_tile(0, 0);
    if (S > 1) load_tile(1, 1);

    int buf = 0;
    for (int s = 0; s < S; s++) {
        if (s < S - 1) { CPWAIT(1); }   // group s complete, s+1 may fly
        else           { CPWAIT(0); }
        __syncthreads();                 // loads visible + prior compute done
        // issue next load BEFORE compute so it overlaps the MMA work
        if (s + 2 < S) {
            int nb = buf + 2; if (nb >= 3) nb -= 3;
            load_tile(s + 2, nb);
        }
        uint32_t bb = smb + buf*BUFB;
#pragma unroll
        for (int kk = 0; kk < 2; kk++) {
            uint32_t ah[4][4], al[4][4], bh[2][4], bl[2][4];
            uint32_t kb = kk*32;
#pragma unroll
            for (int mi = 0; mi < 4; mi++) {
                ldmx4(ah[mi], bb +         aoff[mi] + kb);
                ldmx4(al[mi], bb + TILEB + aoff[mi] + kb);
            }
#pragma unroll
            for (int bg = 0; bg < 2; bg++) {
                ldmx4(bh[bg], bb + 2*TILEB + boff[bg] + kb);
                ldmx4(bl[bg], bb + 3*TILEB + boff[bg] + kb);
            }
#pragma unroll
            for (int mi = 0; mi < 4; mi++)
#pragma unroll
                for (int ni = 0; ni < 4; ni++) {
                    int bg = ni >> 1, sub = (ni & 1)*2;
                    mma16816(acc[mi][ni], ah[mi], bh[bg][sub], bh[bg][sub+1]);
                    mma16816(acc[mi][ni], ah[mi], bl[bg][sub], bl[bg][sub+1]);
                    mma16816(acc[mi][ni], al[mi], bh[bg][sub], bh[bg][sub+1]);
                }
        }
        buf++; if (buf >= 3) buf = 0;
    }
}

// ---------------- init ------------------------------------------------------
__global__ void zero_scalars_k() {
    int i = blockIdx.x*blockDim.x + threadIdx.x;
    if (i == 0) g_w0n2 = 0.0;
    if (i < B_*NPAIR) g_gram[i] = 0.0;
}

// ---------------- ||W0||^2 --------------------------------------------------
__global__ void w0norm_k(const float* __restrict__ W0) {
    __shared__ double sred[256];
    double s = 0.0;
    for (int i = blockIdx.x*blockDim.x + threadIdx.x; i < NE; i += gridDim.x*blockDim.x) {
        float v = W0[i];
        s += (double)v * (double)v;
    }
    sred[threadIdx.x] = s; __syncthreads();
    for (int o = 128; o > 0; o >>= 1) {
        if (threadIdx.x < o) sred[threadIdx.x] += sred[threadIdx.x + o];
        __syncthreads();
    }
    if (threadIdx.x == 0) atomicAdd(&g_w0n2, sred[0]);
}

// ---------------- causal depthwise conv + double rmsnorm -> vu (fp32) -------
__global__ void conv_vu_k(const float* __restrict__ src, const float* __restrict__ cw) {
    int bt = blockIdx.x;
    int b  = bt / T_;
    int t  = bt % T_;
    float vals[4];
    float ss = 0.f;
#pragma unroll
    for (int q = 0; q < 4; q++) {
        int o = threadIdx.x + q*256;
        float acc = 0.f;
#pragma unroll
        for (int j = 0; j < KSZ; j++) {
            int tt = t - (KSZ-1) + j;
            float x = (tt >= 0) ? src[((size_t)b*T_ + tt)*DM + o] : 0.f;
            acc = fmaf(x, cw[o*KSZ + j], acc);
        }
        vals[q] = acc;
        ss += acc*acc;
    }
    __shared__ float red[256];
    red[threadIdx.x] = ss; __syncthreads();
    for (int o = 128; o > 0; o >>= 1) {
        if (threadIdx.x < o) red[threadIdx.x] += red[threadIdx.x + o];
        __syncthreads();
    }
    float ms  = red[0] * (1.0f/DM);
    float s1  = rsqrtf(ms + NORM_EPS);
    float ms2 = ms * s1 * s1;
    float s2  = rsqrtf(ms2 + NORM_EPS);
    float s   = s1 * s2;
#pragma unroll
    for (int q = 0; q < 4; q++) {
        int o = threadIdx.x + q*256;
        g_vu[(size_t)bt*DM + o] = vals[q] * s;
    }
}

// ---------------- rmsnorm(z) -> zu (fp32) -----------------------------------
__global__ void z_rms_k(const float* __restrict__ z) {
    int bt = blockIdx.x;
    const float* row = z + (size_t)bt*DI;
    float vals[8];
    float ss = 0.f;
#pragma unroll
    for (int q = 0; q < 8; q++) {
        int d = threadIdx.x + q*256;
        float v = row[d];
        vals[q] = v;
        ss += v*v;
    }
    __shared__ float red[256];
    red[threadIdx.x] = ss; __syncthreads();
    for (int o = 128; o > 0; o >>= 1) {
        if (threadIdx.x < o) red[threadIdx.x] += red[threadIdx.x + o];
        __syncthreads();
    }
    float s = rsqrtf(red[0]*(1.0f/DI) + NORM_EPS);
#pragma unroll
    for (int q = 0; q < 8; q++) {
        int d = threadIdx.x + q*256;
        g_zu[(size_t)bt*DI + d] = vals[q] * s;
    }
}

// ---------------- split z -> zh/zl (K-major already) ------------------------
__global__ void zsplit_k(const float* __restrict__ z) {
    for (size_t i = (size_t)blockIdx.x*blockDim.x + threadIdx.x;
         i < (size_t)B_*T_*DI; i += (size_t)gridDim.x*blockDim.x) {
        float v = z[i];
        __nv_bfloat16 h = __float2bfloat16(v);
        __nv_bfloat16 l = __float2bfloat16(v - __bfloat162float(h));
        g_zh[i] = h; g_zl[i] = l;
    }
}

// ---------------- transpose + split [b][t][W] -> [b][W][t] bf16 hi/lo -------
// Device globals referenced in DEVICE code only (host-side symbol args alias
// the zero host shadow via ATS — round-6 bug).
__device__ __forceinline__ void tsplit_body(const float* __restrict__ src,
                                            __nv_bfloat16* __restrict__ dh,
                                            __nv_bfloat16* __restrict__ dl, int W) {
    __shared__ float tile[32][33];
    int b  = blockIdx.z;
    int w0 = blockIdx.x*32, t0 = blockIdx.y*32;
    int tid = threadIdx.x;
#pragma unroll
    for (int i = 0; i < 4; i++) {
        int q = tid + i*256; int r = q>>5, c = q&31;
        tile[r][c] = src[((size_t)b*T_ + t0 + r)*W + w0 + c];
    }
    __syncthreads();
#pragma unroll
    for (int i = 0; i < 4; i++) {
        int q = tid + i*256; int c = q>>5, r = q&31;
        float v = tile[r][c];
        __nv_bfloat16 h = __float2bfloat16(v);
        __nv_bfloat16 l = __float2bfloat16(v - __bfloat162float(h));
        size_t o = ((size_t)b*W + w0 + c)*T_ + t0 + r;
        dh[o] = h; dl[o] = l;
    }
}
__global__ void tsplit_vu_k() { tsplit_body(g_vu, g_vuT_h, g_vuT_l, DM); }
__global__ void tsplit_zu_k() { tsplit_body(g_zu, g_zuT_h, g_zuT_l, DI); }

// ---------------- HMMA GEMM: G[o,d] = sum_t vu[t,o] zu[t,d] / C -------------
__global__ void __launch_bounds__(256, 1) gemmG_hmma() {
    extern __shared__ char dsm[];
    uint32_t smb = smem_u32(dsm);
    int bk = blockIdx.z;
    int b = bk >> 4, kc = bk & 15;
    int obase = blockIdx.y*128;
    int dbase = blockIdx.x*128;
    size_t abase = ((size_t)b*DM + obase)*T_ + (size_t)kc*CHK;
    size_t bbase = ((size_t)b*DI + dbase)*T_ + (size_t)kc*CHK;

    float acc[4][4][4];
#pragma unroll
    for (int i = 0; i < 4; i++)
#pragma unroll
        for (int j = 0; j < 4; j++)
#pragma unroll
            for (int r = 0; r < 4; r++) acc[i][j][r] = 0.f;

    gemm_mainloop(g_vuT_h + abase, g_vuT_l + abase, T_,
                  g_zuT_h + bbase, g_zuT_l + bbase, T_, CHK, smb, acc);

    int lane = threadIdx.x & 31, wid = threadIdx.x >> 5;
    int warpM = wid >> 2, warpN = wid & 3;
    int g = lane >> 2, tc = (lane & 3)*2;
    float* Cg = g_G + (size_t)bk*NE;
#pragma unroll
    for (int mi = 0; mi < 4; mi++)
#pragma unroll
        for (int ni = 0; ni < 4; ni++) {
            int r0  = obase + warpM*64 + mi*16 + g;
            int col = dbase + warpN*32 + ni*8 + tc;
            float2 v0 = make_float2(acc[mi][ni][0]*INV_C, acc[mi][ni][1]*INV_C);
            float2 v1 = make_float2(acc[mi][ni][2]*INV_C, acc[mi][ni][3]*INV_C);
            *(float2*)(Cg + (size_t)r0*DI + col)     = v0;
            *(float2*)(Cg + (size_t)(r0+8)*DI + col) = v1;
        }
}

// ---------------- Gram matrix: all 136 pairwise <G_i, G_j> per batch --------
__global__ void __launch_bounds__(128, 1) gram_k() {
    int b = blockIdx.y;
    const float* Gb = g_G + (size_t)b*NC*NE;
    float acc[NPAIR];
#pragma unroll
    for (int p = 0; p < NPAIR; p++) acc[p] = 0.f;

    for (int e = blockIdx.x*128 + threadIdx.x; e < NE; e += gridDim.x*128) {
        float g[NC];
#pragma unroll
        for (int j = 0; j < NC; j++) g[j] = Gb[(size_t)j*NE + e];
        int p = 0;
#pragma unroll
        for (int j = 0; j < NC; j++)
#pragma unroll
            for (int i = 0; i <= j; i++) { acc[p] = fmaf(g[i], g[j], acc[p]); p++; }
    }
    __shared__ float sw[NPAIR*4];
    int lane = threadIdx.x & 31, w = threadIdx.x >> 5;
#pragma unroll
    for (int p = 0; p < NPAIR; p++) {
        float v = acc[p];
        v += __shfl_xor_sync(0xFFFFFFFFu, v, 16);
        v += __shfl_xor_sync(0xFFFFFFFFu, v, 8);
        v += __shfl_xor_sync(0xFFFFFFFFu, v, 4);
        v += __shfl_xor_sync(0xFFFFFFFFu, v, 2);
        v += __shfl_xor_sync(0xFFFFFFFFu, v, 1);
        if (lane == 0) sw[p*4 + w] = v;
    }
    __syncthreads();
    for (int p = threadIdx.x; p < NPAIR; p += 128)
        atomicAdd(&g_gram[b*NPAIR + p],
                  (double)(sw[p*4] + sw[p*4+1] + sw[p*4+2] + sw[p*4+3]));
}

// ---------------- scalar recursion: sA_k, sB_k from Gram --------------------
__global__ void scal2_k(const float* __restrict__ lil, const float* __restrict__ ldl) {
    int b = threadIdx.x;
    if (b >= B_) return;
    double eta   = exp((double)lil[0]);
    double sg    = 1.0/(1.0 + exp(-(double)ldl[0]));
    double decay = 0.9 + (0.995 - 0.9)*sg;
    double W0n   = sqrt(g_w0n2);
    const double* Gm = g_gram + b*NPAIR;
    double beta[NC];
#pragma unroll
    for (int j = 0; j < NC; j++) beta[j] = 0.0;
    double dwn2 = 0.0;
    for (int k = 0; k < NC; k++) {
        int rb = k*(k+1)/2;
        double gn2 = Gm[rb + k];
        double gsc = fmin(0.02*W0n/(sqrt(gn2) + 1e-8), 1.0);
        double c   = (1.0 - decay)*eta*gsc;
        double dot = 0.0;
        for (int j = 0; j < k; j++) dot += beta[j]*Gm[rb + j];
        double in2 = decay*decay*dwn2 + c*c*gn2 + 2.0*decay*c*dot;
        double s   = fmin(0.1*W0n/(sqrt(in2) + 1e-8), 1.0);
        g_sA[b*NC + k] = (float)(s*decay);
        g_sB[b*NC + k] = (float)(s*c);
        for (int j = 0; j < k; j++) beta[j] *= s*decay;
        beta[k] = s*c;
        dwn2 = in2*s*s;
    }
}

// ---------------- materialize W_k = W0 + dW_{k-1} (bf16 split) + deltaW -----
__global__ void matW_k(const float* __restrict__ W0, float* __restrict__ outDW) {
    int b = blockIdx.y;
    __shared__ float sA[NC], sB[NC];
    if (threadIdx.x < NC) { sA[threadIdx.x] = g_sA[b*NC + threadIdx.x];
                            sB[threadIdx.x] = g_sB[b*NC + threadIdx.x]; }
    __syncthreads();
    for (int e = blockIdx.x*blockDim.x + threadIdx.x; e < NE; e += gridDim.x*blockDim.x) {
        float w0 = W0[e];
        float dw = 0.f;
#pragma unroll
        for (int k = 0; k < NC; k++) {
            float w = w0 + dw;
            __nv_bfloat16 h = __float2bfloat16(w);
            __nv_bfloat16 l = __float2bfloat16(w - __bfloat162float(h));
            size_t o = ((size_t)b*NC + k)*NE + e;
            g_Wh[o] = h; g_Wl[o] = l;
            float g = g_G[((size_t)b*NC + k)*NE + e];
            dw = fmaf(sA[k], dw, sB[k]*g);
        }
        outDW[(size_t)b*NE + e] = dw;
    }
}

// ---------------- HMMA GEMM: out[t,o] = z[t,:]·W_k[o,:] + bias, split-K2 ----
__global__ void __launch_bounds__(256, 1) gemmOut_hmma(const float* __restrict__ bias,
                                                       float* __restrict__ out) {
    extern __shared__ char dsm[];
    uint32_t smb = smem_u32(dsm);
    int bz = blockIdx.z;
    int bk = bz >> 1, ks = bz & 1;          // split-K half
    int obase = blockIdx.x*128;
    int tbase = blockIdx.y*128;
    const int KH = DI/2;                     // 1024
    size_t abase = ((size_t)bk*CHK + tbase)*DI + (size_t)ks*KH;
    size_t bbase = (size_t)bk*NE + (size_t)obase*DI + (size_t)ks*KH;

    float acc[4][4][4];
#pragma unroll
    for (int i = 0; i < 4; i++)
#pragma unroll
        for (int j = 0; j < 4; j++)
#pragma unroll
            for (int r = 0; r < 4; r++) acc[i][j][r] = 0.f;

    gemm_mainloop(g_zh + abase, g_zl + abase, DI,
                  g_Wh + bbase, g_Wl + bbase, DI, KH, smb, acc);

    int lane = threadIdx.x & 31, wid = threadIdx.x >> 5;
    int warpM = wid >> 2, warpN = wid & 3;
    int g = lane >> 2, tc = (lane & 3)*2;
    float* dst = (ks == 0) ? out : g_part;
#pragma unroll
    for (int mi = 0; mi < 4; mi++)
#pragma unroll
        for (int ni = 0; ni < 4; ni++) {
            int r0  = tbase + warpM*64 + mi*16 + g;
            int col = obase + warpN*32 + ni*8 + tc;
            float b0 = 0.f, b1 = 0.f;
            if (ks == 0) { b0 = bias[col]; b1 = bias[col+1]; }
            float2 v0 = make_float2(acc[mi][ni][0] + b0, acc[mi][ni][1] + b1);
            float2 v1 = make_float2(acc[mi][ni][2] + b0, acc[mi][ni][3] + b1);
            *(float2*)(dst + ((size_t)bk*CHK + r0)*DM + col)     = v0;
            *(float2*)(dst + ((size_t)bk*CHK + r0 + 8)*DM + col) = v1;
        }
}

// ---------------- split-K reduce: out += g_part ------------------------------
__global__ void addpart_k(float* __restrict__ out) {
    size_t n4 = (size_t)B_*T_*DM/4;
    float4* o4 = (float4*)out;
    for (size_t i = (size_t)blockIdx.x*blockDim.x + threadIdx.x;
         i < n4; i += (size_t)gridDim.x*blockDim.x) {
        float4 a = o4[i];
        float4 p = ((const float4*)g_part)[i];
        a.x += p.x; a.y += p.y; a.z += p.z; a.w += p.w;
        o4[i] = a;
    }
}

// ---------------- launch -----------------------------------------------------
extern "C" void kernel_launch(void* const* d_in, const int* in_sizes, int n_in,
                              void* d_out, int out_size) {
    const float* z    = (const float*)d_in[0];
    const float* src  = (const float*)d_in[1];
    const float* W0   = (const float*)d_in[2];
    const float* bias = (const float*)d_in[3];
    const float* cw   = (const float*)d_in[4];
    const float* lil  = (const float*)d_in[5];
    const float* ldl  = (const float*)d_in[6];
    float* out = (float*)d_out;

    cudaFuncSetAttribute(gemmG_hmma,   cudaFuncAttributeMaxDynamicSharedMemorySize, SMEM_DYN);
    cudaFuncSetAttribute(gemmOut_hmma, cudaFuncAttributeMaxDynamicSharedMemorySize, SMEM_DYN);

    zero_scalars_k<<<2, 256>>>();
    w0norm_k<<<256, 256>>>(W0);
    conv_vu_k<<<B_*T_, 256>>>(src, cw);
    z_rms_k<<<B_*T_, 256>>>(z);
    zsplit_k<<<4096, 256>>>(z);
    tsplit_vu_k<<<dim3(DM/32, T_/32, B_), 256>>>();
    tsplit_zu_k<<<dim3(DI/32, T_/32, B_), 256>>>();

    gemmG_hmma<<<dim3(DI/128, DM/128, B_*NC), 256, SMEM_DYN>>>();

    gram_k<<<dim3(512, B_), 128>>>();
    scal2_k<<<1, 32>>>(lil, ldl);
    matW_k<<<dim3(1024, B_), 256>>>(W0, out + (size_t)B_*T_*DM);

    gemmOut_hmma<<<dim3(DM/128, CHK/128, B_*NC*2), 256, SMEM_DYN>>>(bias, out);
    addpart_k<<<1024, 256>>>(out);
}

// round 9
// speedup vs baseline: 2.0727x; 1.1665x over previous
#include <cuda_runtime.h>
#include <cuda_fp16.h>
#include <stdint.h>
#include <math.h>

#define B_    2
#define T_    4096
#define DM    1024
#define DI    2048
#define CHK   256
#define NC    16
#define KSZ   5
#define NE    (DM*DI)
#define NPAIR 136
#define NORM_EPS 1e-6f
#define INV_C (1.0f/256.0f)

// ---------------- scratch (device globals; no allocation allowed) ----------
__device__ float   g_vu [(size_t)B_*T_*DM];     // conv+double-rms, fp32
__device__ float   g_zu [(size_t)B_*T_*DI];     // rms(z), fp32
__device__ float   g_G  [(size_t)B_*NC*NE];     // G_k (scaled by 1/C), fp32
__device__ float   g_part[(size_t)B_*T_*DM];    // split-K partial for out
__device__ __half  g_vuT_h[(size_t)B_*DM*T_];   // vu^T hi  [b][o][t]
__device__ __half  g_vuT_l[(size_t)B_*DM*T_];   // vu^T lo
__device__ __half  g_zuT_h[(size_t)B_*DI*T_];   // zu^T hi  [b][d][t]  (no lo)
__device__ __half  g_zh [(size_t)B_*T_*DI];     // z hi  [b][t][d]
__device__ __half  g_zl [(size_t)B_*T_*DI];     // z lo
__device__ __half  g_Wh [(size_t)B_*NC*NE];     // fp16(W0+dW_{k-1}) [b][k][o][d]
__device__ double  g_gram[B_*NPAIR];
__device__ double  g_w0n2;
__device__ float   g_sA[B_*NC];
__device__ float   g_sB[B_*NC];

// ---------------- mma.sync / cp.async helpers (sm_80+, NOT arch-'a') -------
__device__ __forceinline__ uint32_t smem_u32(const void* p) {
    uint32_t a;
    asm("{ .reg .u64 t; cvta.to.shared.u64 t, %1; cvt.u32.u64 %0, t; }"
        : "=r"(a) : "l"(p));
    return a;
}
__device__ __forceinline__ void ldmx4(uint32_t r[4], uint32_t addr) {
    asm volatile("ldmatrix.sync.aligned.m8n8.x4.shared.b16 {%0,%1,%2,%3}, [%4];"
        : "=r"(r[0]), "=r"(r[1]), "=r"(r[2]), "=r"(r[3]) : "r"(addr));
}
__device__ __forceinline__ void mma16816(float c[4], const uint32_t a[4],
                                         uint32_t b0, uint32_t b1) {
    asm volatile("mma.sync.aligned.m16n8k16.row.col.f32.f16.f16.f32 "
        "{%0,%1,%2,%3}, {%4,%5,%6,%7}, {%8,%9}, {%0,%1,%2,%3};"
        : "+f"(c[0]), "+f"(c[1]), "+f"(c[2]), "+f"(c[3])
        : "r"(a[0]), "r"(a[1]), "r"(a[2]), "r"(a[3]), "r"(b0), "r"(b1));
}
#define CPASYNC16(dst, src) \
    asm volatile("cp.async.cg.shared.global [%0], [%1], 16;" :: "r"(dst), "l"(src))
#define CPCOMMIT() asm volatile("cp.async.commit_group;")
#define CPWAIT(n)  asm volatile("cp.async.wait_group %0;" :: "n"(n))

// smem: 3 operand tiles (Ah,Al,Bh), each 128 rows x 32 fp16, row stride 80B
#define SROW   80
#define TILEB  (128*SROW)     // 10240
#define BUFB   (3*TILEB)      // 30720
#define SMEM_DYN (3*BUFB)     // 92160 (3-stage pipeline)

// ---------------- shared GEMM mainloop (128x128 tile, BK=32,
//                  fp16 2-term split: D = Ah*Bh + Al*Bh) --------------------
__device__ __forceinline__ void gemm_mainloop(
    const __half* __restrict__ Ah, const __half* __restrict__ Al, int lda,
    const __half* __restrict__ Bh, int ldb,
    int K, uint32_t smb, float acc[4][4][4])
{
    int tid = threadIdx.x, lane = tid & 31, wid = tid >> 5;
    int warpM = wid >> 2, warpN = wid & 3;
    const int S = K / 32;

    int q0r = tid >> 2,          q0c = tid & 3;
    int q1r = (tid + 256) >> 2,  q1c = tid & 3;

    uint32_t aoff[4], boff[2];
#pragma unroll
    for (int mi = 0; mi < 4; mi++)
        aoff[mi] = (uint32_t)(warpM*64 + mi*16 + (lane & 15))*SROW + ((lane >> 4) & 1)*16;
#pragma unroll
    for (int bg = 0; bg < 2; bg++)
        boff[bg] = (uint32_t)(warpN*32 + bg*16 + (lane & 7) + ((lane & 16) ? 8 : 0))*SROW
                 + ((lane >> 3) & 1)*16;

    auto load_tile = [&](int s, int buf) {
        int k0 = s*32;
        uint32_t bb = smb + buf*BUFB;
        CPASYNC16(bb +            q0r*SROW + q0c*16, Ah + (size_t)q0r*lda + k0 + q0c*8);
        CPASYNC16(bb +            q1r*SROW + q1c*16, Ah + (size_t)q1r*lda + k0 + q1c*8);
        CPASYNC16(bb +   TILEB +  q0r*SROW + q0c*16, Al + (size_t)q0r*lda + k0 + q0c*8);
        CPASYNC16(bb +   TILEB +  q1r*SROW + q1c*16, Al + (size_t)q1r*lda + k0 + q1c*8);
        CPASYNC16(bb + 2*TILEB +  q0r*SROW + q0c*16, Bh + (size_t)q0r*ldb + k0 + q0c*8);
        CPASYNC16(bb + 2*TILEB +  q1r*SROW + q1c*16, Bh + (size_t)q1r*ldb + k0 + q1c*8);
        CPCOMMIT();
    };

    load_tile(0, 0);
    if (S > 1) load_tile(1, 1);

    int buf = 0;
    for (int s = 0; s < S; s++) {
        if (s < S - 1) { CPWAIT(1); }
        else           { CPWAIT(0); }
        __syncthreads();
        if (s + 2 < S) {
            int nb = buf + 2; if (nb >= 3) nb -= 3;
            load_tile(s + 2, nb);
        }
        uint32_t bb = smb + buf*BUFB;
#pragma unroll
        for (int kk = 0; kk < 2; kk++) {
            uint32_t ah[4][4], al[4][4], bh[2][4];
            uint32_t kb = kk*32;
#pragma unroll
            for (int mi = 0; mi < 4; mi++) {
                ldmx4(ah[mi], bb +         aoff[mi] + kb);
                ldmx4(al[mi], bb + TILEB + aoff[mi] + kb);
            }
#pragma unroll
            for (int bg = 0; bg < 2; bg++)
                ldmx4(bh[bg], bb + 2*TILEB + boff[bg] + kb);
#pragma unroll
            for (int mi = 0; mi < 4; mi++)
#pragma unroll
                for (int ni = 0; ni < 4; ni++) {
                    int bg = ni >> 1, sub = (ni & 1)*2;
                    mma16816(acc[mi][ni], ah[mi], bh[bg][sub], bh[bg][sub+1]);
                    mma16816(acc[mi][ni], al[mi], bh[bg][sub], bh[bg][sub+1]);
                }
        }
        buf++; if (buf >= 3) buf = 0;
    }
}

// ---------------- init ------------------------------------------------------
__global__ void zero_scalars_k() {
    int i = blockIdx.x*blockDim.x + threadIdx.x;
    if (i == 0) g_w0n2 = 0.0;
    if (i < B_*NPAIR) g_gram[i] = 0.0;
}

// ---------------- ||W0||^2 --------------------------------------------------
__global__ void w0norm_k(const float* __restrict__ W0) {
    __shared__ double sred[256];
    double s = 0.0;
    for (int i = blockIdx.x*blockDim.x + threadIdx.x; i < NE; i += gridDim.x*blockDim.x) {
        float v = W0[i];
        s += (double)v * (double)v;
    }
    sred[threadIdx.x] = s; __syncthreads();
    for (int o = 128; o > 0; o >>= 1) {
        if (threadIdx.x < o) sred[threadIdx.x] += sred[threadIdx.x + o];
        __syncthreads();
    }
    if (threadIdx.x == 0) atomicAdd(&g_w0n2, sred[0]);
}

// ---------------- causal depthwise conv + double rmsnorm -> vu (fp32) -------
__global__ void conv_vu_k(const float* __restrict__ src, const float* __restrict__ cw) {
    int bt = blockIdx.x;
    int b  = bt / T_;
    int t  = bt % T_;
    float vals[4];
    float ss = 0.f;
#pragma unroll
    for (int q = 0; q < 4; q++) {
        int o = threadIdx.x + q*256;
        float acc = 0.f;
#pragma unroll
        for (int j = 0; j < KSZ; j++) {
            int tt = t - (KSZ-1) + j;
            float x = (tt >= 0) ? src[((size_t)b*T_ + tt)*DM + o] : 0.f;
            acc = fmaf(x, cw[o*KSZ + j], acc);
        }
        vals[q] = acc;
        ss += acc*acc;
    }
    __shared__ float red[256];
    red[threadIdx.x] = ss; __syncthreads();
    for (int o = 128; o > 0; o >>= 1) {
        if (threadIdx.x < o) red[threadIdx.x] += red[threadIdx.x + o];
        __syncthreads();
    }
    float ms  = red[0] * (1.0f/DM);
    float s1  = rsqrtf(ms + NORM_EPS);
    float ms2 = ms * s1 * s1;
    float s2  = rsqrtf(ms2 + NORM_EPS);
    float s   = s1 * s2;
#pragma unroll
    for (int q = 0; q < 4; q++) {
        int o = threadIdx.x + q*256;
        g_vu[(size_t)bt*DM + o] = vals[q] * s;
    }
}

// ---------------- rmsnorm(z) -> zu (fp32) -----------------------------------
__global__ void z_rms_k(const float* __restrict__ z) {
    int bt = blockIdx.x;
    const float* row = z + (size_t)bt*DI;
    float vals[8];
    float ss = 0.f;
#pragma unroll
    for (int q = 0; q < 8; q++) {
        int d = threadIdx.x + q*256;
        float v = row[d];
        vals[q] = v;
        ss += v*v;
    }
    __shared__ float red[256];
    red[threadIdx.x] = ss; __syncthreads();
    for (int o = 128; o > 0; o >>= 1) {
        if (threadIdx.x < o) red[threadIdx.x] += red[threadIdx.x + o];
        __syncthreads();
    }
    float s = rsqrtf(red[0]*(1.0f/DI) + NORM_EPS);
#pragma unroll
    for (int q = 0; q < 8; q++) {
        int d = threadIdx.x + q*256;
        g_zu[(size_t)bt*DI + d] = vals[q] * s;
    }
}

// ---------------- split z -> zh/zl (fp16 hi/lo, K-major already) ------------
__global__ void zsplit_k(const float* __restrict__ z) {
    for (size_t i = (size_t)blockIdx.x*blockDim.x + threadIdx.x;
         i < (size_t)B_*T_*DI; i += (size_t)gridDim.x*blockDim.x) {
        float v = z[i];
        __half h = __float2half_rn(v);
        __half l = __float2half_rn(v - __half2float(h));
        g_zh[i] = h; g_zl[i] = l;
    }
}

// ---------------- transpose + split [b][t][W] -> [b][W][t] fp16 -------------
// Device globals referenced in DEVICE code only (ATS host-shadow trap).
template <bool WRITE_LO>
__device__ __forceinline__ void tsplit_body(const float* __restrict__ src,
                                            __half* __restrict__ dh,
                                            __half* __restrict__ dl, int W) {
    __shared__ float tile[32][33];
    int b  = blockIdx.z;
    int w0 = blockIdx.x*32, t0 = blockIdx.y*32;
    int tid = threadIdx.x;
#pragma unroll
    for (int i = 0; i < 4; i++) {
        int q = tid + i*256; int r = q>>5, c = q&31;
        tile[r][c] = src[((size_t)b*T_ + t0 + r)*W + w0 + c];
    }
    __syncthreads();
#pragma unroll
    for (int i = 0; i < 4; i++) {
        int q = tid + i*256; int c = q>>5, r = q&31;
        float v = tile[r][c];
        __half h = __float2half_rn(v);
        size_t o = ((size_t)b*W + w0 + c)*T_ + t0 + r;
        dh[o] = h;
        if (WRITE_LO) dl[o] = __float2half_rn(v - __half2float(h));
    }
}
__global__ void tsplit_vu_k() { tsplit_body<true >(g_vu, g_vuT_h, g_vuT_l, DM); }
__global__ void tsplit_zu_k() { tsplit_body<false>(g_zu, g_zuT_h, nullptr, DI); }

// ---------------- HMMA GEMM: G[o,d] = sum_t vu[t,o] zu[t,d] / C -------------
__global__ void __launch_bounds__(256, 1) gemmG_hmma() {
    extern __shared__ char dsm[];
    uint32_t smb = smem_u32(dsm);
    int bk = blockIdx.z;
    int b = bk >> 4, kc = bk & 15;
    int obase = blockIdx.y*128;
    int dbase = blockIdx.x*128;
    size_t abase = ((size_t)b*DM + obase)*T_ + (size_t)kc*CHK;
    size_t bbase = ((size_t)b*DI + dbase)*T_ + (size_t)kc*CHK;

    float acc[4][4][4];
#pragma unroll
    for (int i = 0; i < 4; i++)
#pragma unroll
        for (int j = 0; j < 4; j++)
#pragma unroll
            for (int r = 0; r < 4; r++) acc[i][j][r] = 0.f;

    gemm_mainloop(g_vuT_h + abase, g_vuT_l + abase, T_,
                  g_zuT_h + bbase, T_, CHK, smb, acc);

    int lane = threadIdx.x & 31, wid = threadIdx.x >> 5;
    int warpM = wid >> 2, warpN = wid & 3;
    int g = lane >> 2, tc = (lane & 3)*2;
    float* Cg = g_G + (size_t)bk*NE;
#pragma unroll
    for (int mi = 0; mi < 4; mi++)
#pragma unroll
        for (int ni = 0; ni < 4; ni++) {
            int r0  = obase + warpM*64 + mi*16 + g;
            int col = dbase + warpN*32 + ni*8 + tc;
            float2 v0 = make_float2(acc[mi][ni][0]*INV_C, acc[mi][ni][1]*INV_C);
            float2 v1 = make_float2(acc[mi][ni][2]*INV_C, acc[mi][ni][3]*INV_C);
            *(float2*)(Cg + (size_t)r0*DI + col)     = v0;
            *(float2*)(Cg + (size_t)(r0+8)*DI + col) = v1;
        }
}

// ---------------- Gram matrix: all 136 pairwise <G_i, G_j> per batch --------
__global__ void __launch_bounds__(128, 1) gram_k() {
    int b = blockIdx.y;
    const float* Gb = g_G + (size_t)b*NC*NE;
    float acc[NPAIR];
#pragma unroll
    for (int p = 0; p < NPAIR; p++) acc[p] = 0.f;

    for (int e = blockIdx.x*128 + threadIdx.x; e < NE; e += gridDim.x*128) {
        float g[NC];
#pragma unroll
        for (int j = 0; j < NC; j++) g[j] = Gb[(size_t)j*NE + e];
        int p = 0;
#pragma unroll
        for (int j = 0; j < NC; j++)
#pragma unroll
            for (int i = 0; i <= j; i++) { acc[p] = fmaf(g[i], g[j], acc[p]); p++; }
    }
    __shared__ float sw[NPAIR*4];
    int lane = threadIdx.x & 31, w = threadIdx.x >> 5;
#pragma unroll
    for (int p = 0; p < NPAIR; p++) {
        float v = acc[p];
        v += __shfl_xor_sync(0xFFFFFFFFu, v, 16);
        v += __shfl_xor_sync(0xFFFFFFFFu, v, 8);
        v += __shfl_xor_sync(0xFFFFFFFFu, v, 4);
        v += __shfl_xor_sync(0xFFFFFFFFu, v, 2);
        v += __shfl_xor_sync(0xFFFFFFFFu, v, 1);
        if (lane == 0) sw[p*4 + w] = v;
    }
    __syncthreads();
    for (int p = threadIdx.x; p < NPAIR; p += 128)
        atomicAdd(&g_gram[b*NPAIR + p],
                  (double)(sw[p*4] + sw[p*4+1] + sw[p*4+2] + sw[p*4+3]));
}

// ---------------- scalar recursion: sA_k, sB_k from Gram --------------------
__global__ void scal2_k(const float* __restrict__ lil, const float* __restrict__ ldl) {
    int b = threadIdx.x;
    if (b >= B_) return;
    double eta   = exp((double)lil[0]);
    double sg    = 1.0/(1.0 + exp(-(double)ldl[0]));
    double decay = 0.9 + (0.995 - 0.9)*sg;
    double W0n   = sqrt(g_w0n2);
    const double* Gm = g_gram + b*NPAIR;
    double beta[NC];
#pragma unroll
    for (int j = 0; j < NC; j++) beta[j] = 0.0;
    double dwn2 = 0.0;
    for (int k = 0; k < NC; k++) {
        int rb = k*(k+1)/2;
        double gn2 = Gm[rb + k];
        double gsc = fmin(0.02*W0n/(sqrt(gn2) + 1e-8), 1.0);
        double c   = (1.0 - decay)*eta*gsc;
        double dot = 0.0;
        for (int j = 0; j < k; j++) dot += beta[j]*Gm[rb + j];
        double in2 = decay*decay*dwn2 + c*c*gn2 + 2.0*decay*c*dot;
        double s   = fmin(0.1*W0n/(sqrt(in2) + 1e-8), 1.0);
        g_sA[b*NC + k] = (float)(s*decay);
        g_sB[b*NC + k] = (float)(s*c);
        for (int j = 0; j < k; j++) beta[j] *= s*decay;
        beta[k] = s*c;
        dwn2 = in2*s*s;
    }
}

// ---------------- materialize W_k = fp16(W0 + dW_{k-1}) + deltaW ------------
__global__ void matW_k(const float* __restrict__ W0, float* __restrict__ outDW) {
    int b = blockIdx.y;
    __shared__ float sA[NC], sB[NC];
    if (threadIdx.x < NC) { sA[threadIdx.x] = g_sA[b*NC + threadIdx.x];
                            sB[threadIdx.x] = g_sB[b*NC + threadIdx.x]; }
    __syncthreads();
    for (int e = blockIdx.x*blockDim.x + threadIdx.x; e < NE; e += gridDim.x*blockDim.x) {
        float w0 = W0[e];
        float dw = 0.f;
#pragma unroll
        for (int k = 0; k < NC; k++) {
            float w = w0 + dw;
            g_Wh[((size_t)b*NC + k)*NE + e] = __float2half_rn(w);
            float g = g_G[((size_t)b*NC + k)*NE + e];
            dw = fmaf(sA[k], dw, sB[k]*g);
        }
        outDW[(size_t)b*NE + e] = dw;
    }
}

// ---------------- HMMA GEMM: out[t,o] = z[t,:]·W_k[o,:] + bias, split-K2 ----
__global__ void __launch_bounds__(256, 1) gemmOut_hmma(const float* __restrict__ bias,
                                                       float* __restrict__ out) {
    extern __shared__ char dsm[];
    uint32_t smb = smem_u32(dsm);
    int bz = blockIdx.z;
    int bk = bz >> 1, ks = bz & 1;          // split-K half
    int obase = blockIdx.x*128;
    int tbase = blockIdx.y*128;
    const int KH = DI/2;                     // 1024
    size_t abase = ((size_t)bk*CHK + tbase)*DI + (size_t)ks*KH;
    size_t bbase = (size_t)bk*NE + (size_t)obase*DI + (size_t)ks*KH;

    float acc[4][4][4];
#pragma unroll
    for (int i = 0; i < 4; i++)
#pragma unroll
        for (int j = 0; j < 4; j++)
#pragma unroll
            for (int r = 0; r < 4; r++) acc[i][j][r] = 0.f;

    gemm_mainloop(g_zh + abase, g_zl + abase, DI,
                  g_Wh + bbase, DI, KH, smb, acc);

    int lane = threadIdx.x & 31, wid = threadIdx.x >> 5;
    int warpM = wid >> 2, warpN = wid & 3;
    int g = lane >> 2, tc = (lane & 3)*2;
    float* dst = (ks == 0) ? out : g_part;
#pragma unroll
    for (int mi = 0; mi < 4; mi++)
#pragma unroll
        for (int ni = 0; ni < 4; ni++) {
            int r0  = tbase + warpM*64 + mi*16 + g;
            int col = obase + warpN*32 + ni*8 + tc;
            float b0 = 0.f, b1 = 0.f;
            if (ks == 0) { b0 = bias[col]; b1 = bias[col+1]; }
            float2 v0 = make_float2(acc[mi][ni][0] + b0, acc[mi][ni][1] + b1);
            float2 v1 = make_float2(acc[mi][ni][2] + b0, acc[mi][ni][3] + b1);
            *(float2*)(dst + ((size_t)bk*CHK + r0)*DM + col)     = v0;
            *(float2*)(dst + ((size_t)bk*CHK + r0 + 8)*DM + col) = v1;
        }
}

// ---------------- split-K reduce: out += g_part ------------------------------
__global__ void addpart_k(float* __restrict__ out) {
    size_t n4 = (size_t)B_*T_*DM/4;
    float4* o4 = (float4*)out;
    for (size_t i = (size_t)blockIdx.x*blockDim.x + threadIdx.x;
         i < n4; i += (size_t)gridDim.x*blockDim.x) {
        float4 a = o4[i];
        float4 p = ((const float4*)g_part)[i];
        a.x += p.x; a.y += p.y; a.z += p.z; a.w += p.w;
        o4[i] = a;
    }
}

// ---------------- launch -----------------------------------------------------
extern "C" void kernel_launch(void* const* d_in, const int* in_sizes, int n_in,
                              void* d_out, int out_size) {
    const float* z    = (const float*)d_in[0];
    const float* src  = (const float*)d_in[1];
    const float* W0   = (const float*)d_in[2];
    const float* bias = (const float*)d_in[3];
    const float* cw   = (const float*)d_in[4];
    const float* lil  = (const float*)d_in[5];
    const float* ldl  = (const float*)d_in[6];
    float* out = (float*)d_out;

    cudaFuncSetAttribute(gemmG_hmma,   cudaFuncAttributeMaxDynamicSharedMemorySize, SMEM_DYN);
    cudaFuncSetAttribute(gemmOut_hmma, cudaFuncAttributeMaxDynamicSharedMemorySize, SMEM_DYN);

    zero_scalars_k<<<2, 256>>>();
    w0norm_k<<<256, 256>>>(W0);
    conv_vu_k<<<B_*T_, 256>>>(src, cw);
    z_rms_k<<<B_*T_, 256>>>(z);
    zsplit_k<<<4096, 256>>>(z);
    tsplit_vu_k<<<dim3(DM/32, T_/32, B_), 256>>>();
    tsplit_zu_k<<<dim3(DI/32, T_/32, B_), 256>>>();

    gemmG_hmma<<<dim3(DI/128, DM/128, B_*NC), 256, SMEM_DYN>>>();

    gram_k<<<dim3(512, B_), 128>>>();
    scal2_k<<<1, 32>>>(lil, ldl);
    matW_k<<<dim3(1024, B_), 256>>>(W0, out + (size_t)B_*T_*DM);

    gemmOut_hmma<<<dim3(DM/128, CHK/128, B_*NC*2), 256, SMEM_DYN>>>(bias, out);
    addpart_k<<<1024, 256>>>(out);
}

// round 10
// speedup vs baseline: 2.3504x; 1.1340x over previous
#include <cuda_runtime.h>
#include <cuda_fp16.h>
#include <stdint.h>
#include <math.h>

#define B_    2
#define T_    4096
#define DM    1024
#define DI    2048
#define CHK   256
#define NC    16
#define KSZ   5
#define NE    (DM*DI)
#define NPAIR 136
#define NORM_EPS 1e-6f
#define INV_C (1.0f/256.0f)

// ---------------- scratch (device globals; no allocation allowed) ----------
__device__ float   g_vu [(size_t)B_*T_*DM];     // conv+double-rms, fp32
__device__ float   g_zu [(size_t)B_*T_*DI];     // rms(z), fp32
__device__ __half  g_G  [(size_t)B_*NC*NE];     // G_k (scaled by 1/C), fp16
__device__ float   g_part[(size_t)B_*T_*DM];    // split-K partial for out
__device__ __half  g_vuT_h[(size_t)B_*DM*T_];   // vu^T hi  [b][o][t]
__device__ __half  g_vuT_l[(size_t)B_*DM*T_];   // vu^T lo
__device__ __half  g_zuT_h[(size_t)B_*DI*T_];   // zu^T hi  [b][d][t]  (no lo)
__device__ __half  g_zh [(size_t)B_*T_*DI];     // z hi  [b][t][d]
__device__ __half  g_zl [(size_t)B_*T_*DI];     // z lo
__device__ __half  g_Wh [(size_t)B_*NC*NE];     // fp16(W0+dW_{k-1}) [b][k][o][d]
__device__ double  g_gram[B_*NPAIR];
__device__ double  g_w0n2;
__device__ float   g_sA[B_*NC];
__device__ float   g_sB[B_*NC];

// ---------------- mma.sync / cp.async helpers (sm_80+, NOT arch-'a') -------
__device__ __forceinline__ uint32_t smem_u32(const void* p) {
    uint32_t a;
    asm("{ .reg .u64 t; cvta.to.shared.u64 t, %1; cvt.u32.u64 %0, t; }"
        : "=r"(a) : "l"(p));
    return a;
}
__device__ __forceinline__ void ldmx4(uint32_t r[4], uint32_t addr) {
    asm volatile("ldmatrix.sync.aligned.m8n8.x4.shared.b16 {%0,%1,%2,%3}, [%4];"
        : "=r"(r[0]), "=r"(r[1]), "=r"(r[2]), "=r"(r[3]) : "r"(addr));
}
__device__ __forceinline__ void mma16816(float c[4], const uint32_t a[4],
                                         uint32_t b0, uint32_t b1) {
    asm volatile("mma.sync.aligned.m16n8k16.row.col.f32.f16.f16.f32 "
        "{%0,%1,%2,%3}, {%4,%5,%6,%7}, {%8,%9}, {%0,%1,%2,%3};"
        : "+f"(c[0]), "+f"(c[1]), "+f"(c[2]), "+f"(c[3])
        : "r"(a[0]), "r"(a[1]), "r"(a[2]), "r"(a[3]), "r"(b0), "r"(b1));
}
#define CPASYNC16(dst, src) \
    asm volatile("cp.async.cg.shared.global [%0], [%1], 16;" :: "r"(dst), "l"(src))
#define CPCOMMIT() asm volatile("cp.async.commit_group;")
#define CPWAIT(n)  asm volatile("cp.async.wait_group %0;" :: "n"(n))

// smem: 3 operand tiles (Ah,Al,Bh), each 128 rows x 32 fp16, row stride 80B
#define SROW   80
#define TILEB  (128*SROW)     // 10240
#define BUFB   (3*TILEB)      // 30720
#define SMEM_DYN (3*BUFB)     // 92160 (3-stage pipeline); x2 blocks = 184320

// ---------------- shared GEMM mainloop (128x128 tile, BK=32,
//                  fp16 2-term split: D = Ah*Bh + Al*Bh) --------------------
__device__ __forceinline__ void gemm_mainloop(
    const __half* __restrict__ Ah, const __half* __restrict__ Al, int lda,
    const __half* __restrict__ Bh, int ldb,
    int K, uint32_t smb, float acc[4][4][4])
{
    int tid = threadIdx.x, lane = tid & 31, wid = tid >> 5;
    int warpM = wid >> 2, warpN = wid & 3;
    const int S = K / 32;

    int q0r = tid >> 2,          q0c = tid & 3;
    int q1r = (tid + 256) >> 2,  q1c = tid & 3;

    uint32_t aoff[4], boff[2];
#pragma unroll
    for (int mi = 0; mi < 4; mi++)
        aoff[mi] = (uint32_t)(warpM*64 + mi*16 + (lane & 15))*SROW + ((lane >> 4) & 1)*16;
#pragma unroll
    for (int bg = 0; bg < 2; bg++)
        boff[bg] = (uint32_t)(warpN*32 + bg*16 + (lane & 7) + ((lane & 16) ? 8 : 0))*SROW
                 + ((lane >> 3) & 1)*16;

    auto load_tile = [&](int s, int buf) {
        int k0 = s*32;
        uint32_t bb = smb + buf*BUFB;
        CPASYNC16(bb +            q0r*SROW + q0c*16, Ah + (size_t)q0r*lda + k0 + q0c*8);
        CPASYNC16(bb +            q1r*SROW + q1c*16, Ah + (size_t)q1r*lda + k0 + q1c*8);
        CPASYNC16(bb +   TILEB +  q0r*SROW + q0c*16, Al + (size_t)q0r*lda + k0 + q0c*8);
        CPASYNC16(bb +   TILEB +  q1r*SROW + q1c*16, Al + (size_t)q1r*lda + k0 + q1c*8);
        CPASYNC16(bb + 2*TILEB +  q0r*SROW + q0c*16, Bh + (size_t)q0r*ldb + k0 + q0c*8);
        CPASYNC16(bb + 2*TILEB +  q1r*SROW + q1c*16, Bh + (size_t)q1r*ldb + k0 + q1c*8);
        CPCOMMIT();
    };

    load_tile(0, 0);
    if (S > 1) load_tile(1, 1);

    int buf = 0;
    for (int s = 0; s < S; s++) {
        if (s < S - 1) { CPWAIT(1); }
        else           { CPWAIT(0); }
        __syncthreads();
        if (s + 2 < S) {
            int nb = buf + 2; if (nb >= 3) nb -= 3;
            load_tile(s + 2, nb);
        }
        uint32_t bb = smb + buf*BUFB;
#pragma unroll
        for (int kk = 0; kk < 2; kk++) {
            uint32_t ah[4][4], al[4][4], bh[2][4];
            uint32_t kb = kk*32;
#pragma unroll
            for (int mi = 0; mi < 4; mi++) {
                ldmx4(ah[mi], bb +         aoff[mi] + kb);
                ldmx4(al[mi], bb + TILEB + aoff[mi] + kb);
            }
#pragma unroll
            for (int bg = 0; bg < 2; bg++)
                ldmx4(bh[bg], bb + 2*TILEB + boff[bg] + kb);
#pragma unroll
            for (int mi = 0; mi < 4; mi++)
#pragma unroll
                for (int ni = 0; ni < 4; ni++) {
                    int bg = ni >> 1, sub = (ni & 1)*2;
                    mma16816(acc[mi][ni], ah[mi], bh[bg][sub], bh[bg][sub+1]);
                    mma16816(acc[mi][ni], al[mi], bh[bg][sub], bh[bg][sub+1]);
                }
        }
        buf++; if (buf >= 3) buf = 0;
    }
}

// ---------------- init ------------------------------------------------------
__global__ void zero_scalars_k() {
    int i = blockIdx.x*blockDim.x + threadIdx.x;
    if (i == 0) g_w0n2 = 0.0;
    if (i < B_*NPAIR) g_gram[i] = 0.0;
}

// ---------------- ||W0||^2 --------------------------------------------------
__global__ void w0norm_k(const float* __restrict__ W0) {
    __shared__ double sred[256];
    double s = 0.0;
    for (int i = blockIdx.x*blockDim.x + threadIdx.x; i < NE; i += gridDim.x*blockDim.x) {
        float v = W0[i];
        s += (double)v * (double)v;
    }
    sred[threadIdx.x] = s; __syncthreads();
    for (int o = 128; o > 0; o >>= 1) {
        if (threadIdx.x < o) sred[threadIdx.x] += sred[threadIdx.x + o];
        __syncthreads();
    }
    if (threadIdx.x == 0) atomicAdd(&g_w0n2, sred[0]);
}

// ---------------- causal depthwise conv + double rmsnorm -> vu (fp32) -------
__global__ void conv_vu_k(const float* __restrict__ src, const float* __restrict__ cw) {
    int bt = blockIdx.x;
    int b  = bt / T_;
    int t  = bt % T_;
    float vals[4];
    float ss = 0.f;
#pragma unroll
    for (int q = 0; q < 4; q++) {
        int o = threadIdx.x + q*256;
        float acc = 0.f;
#pragma unroll
        for (int j = 0; j < KSZ; j++) {
            int tt = t - (KSZ-1) + j;
            float x = (tt >= 0) ? src[((size_t)b*T_ + tt)*DM + o] : 0.f;
            acc = fmaf(x, cw[o*KSZ + j], acc);
        }
        vals[q] = acc;
        ss += acc*acc;
    }
    __shared__ float red[256];
    red[threadIdx.x] = ss; __syncthreads();
    for (int o = 128; o > 0; o >>= 1) {
        if (threadIdx.x < o) red[threadIdx.x] += red[threadIdx.x + o];
        __syncthreads();
    }
    float ms  = red[0] * (1.0f/DM);
    float s1  = rsqrtf(ms + NORM_EPS);
    float ms2 = ms * s1 * s1;
    float s2  = rsqrtf(ms2 + NORM_EPS);
    float s   = s1 * s2;
#pragma unroll
    for (int q = 0; q < 4; q++) {
        int o = threadIdx.x + q*256;
        g_vu[(size_t)bt*DM + o] = vals[q] * s;
    }
}

// ---------------- rmsnorm(z) -> zu (fp32) + z hi/lo split (fused) -----------
__global__ void z_rms_k(const float* __restrict__ z) {
    int bt = blockIdx.x;
    const float* row = z + (size_t)bt*DI;
    float vals[8];
    float ss = 0.f;
#pragma unroll
    for (int q = 0; q < 8; q++) {
        int d = threadIdx.x + q*256;
        float v = row[d];
        vals[q] = v;
        ss += v*v;
    }
    __shared__ float red[256];
    red[threadIdx.x] = ss; __syncthreads();
    for (int o = 128; o > 0; o >>= 1) {
        if (threadIdx.x < o) red[threadIdx.x] += red[threadIdx.x + o];
        __syncthreads();
    }
    float s = rsqrtf(red[0]*(1.0f/DI) + NORM_EPS);
#pragma unroll
    for (int q = 0; q < 8; q++) {
        int d = threadIdx.x + q*256;
        float v = vals[q];
        g_zu[(size_t)bt*DI + d] = v * s;
        __half h = __float2half_rn(v);
        g_zh[(size_t)bt*DI + d] = h;
        g_zl[(size_t)bt*DI + d] = __float2half_rn(v - __half2float(h));
    }
}

// ---------------- transpose + split [b][t][W] -> [b][W][t] fp16 -------------
// Device globals referenced in DEVICE code only (ATS host-shadow trap).
template <bool WRITE_LO>
__device__ __forceinline__ void tsplit_body(const float* __restrict__ src,
                                            __half* __restrict__ dh,
                                            __half* __restrict__ dl, int W) {
    __shared__ float tile[32][33];
    int b  = blockIdx.z;
    int w0 = blockIdx.x*32, t0 = blockIdx.y*32;
    int tid = threadIdx.x;
#pragma unroll
    for (int i = 0; i < 4; i++) {
        int q = tid + i*256; int r = q>>5, c = q&31;
        tile[r][c] = src[((size_t)b*T_ + t0 + r)*W + w0 + c];
    }
    __syncthreads();
#pragma unroll
    for (int i = 0; i < 4; i++) {
        int q = tid + i*256; int c = q>>5, r = q&31;
        float v = tile[r][c];
        __half h = __float2half_rn(v);
        size_t o = ((size_t)b*W + w0 + c)*T_ + t0 + r;
        dh[o] = h;
        if (WRITE_LO) dl[o] = __float2half_rn(v - __half2float(h));
    }
}
__global__ void tsplit_vu_k() { tsplit_body<true >(g_vu, g_vuT_h, g_vuT_l, DM); }
__global__ void tsplit_zu_k() { tsplit_body<false>(g_zu, g_zuT_h, nullptr, DI); }

// ---------------- HMMA GEMM: G[o,d] = sum_t vu[t,o] zu[t,d] / C -------------
__global__ void __launch_bounds__(256, 2) gemmG_hmma() {
    extern __shared__ char dsm[];
    uint32_t smb = smem_u32(dsm);
    int bk = blockIdx.z;
    int b = bk >> 4, kc = bk & 15;
    int obase = blockIdx.y*128;
    int dbase = blockIdx.x*128;
    size_t abase = ((size_t)b*DM + obase)*T_ + (size_t)kc*CHK;
    size_t bbase = ((size_t)b*DI + dbase)*T_ + (size_t)kc*CHK;

    float acc[4][4][4];
#pragma unroll
    for (int i = 0; i < 4; i++)
#pragma unroll
        for (int j = 0; j < 4; j++)
#pragma unroll
            for (int r = 0; r < 4; r++) acc[i][j][r] = 0.f;

    gemm_mainloop(g_vuT_h + abase, g_vuT_l + abase, T_,
                  g_zuT_h + bbase, T_, CHK, smb, acc);

    int lane = threadIdx.x & 31, wid = threadIdx.x >> 5;
    int warpM = wid >> 2, warpN = wid & 3;
    int g = lane >> 2, tc = (lane & 3)*2;
    __half* Cg = g_G + (size_t)bk*NE;
#pragma unroll
    for (int mi = 0; mi < 4; mi++)
#pragma unroll
        for (int ni = 0; ni < 4; ni++) {
            int r0  = obase + warpM*64 + mi*16 + g;
            int col = dbase + warpN*32 + ni*8 + tc;
            __half2 v0 = __floats2half2_rn(acc[mi][ni][0]*INV_C, acc[mi][ni][1]*INV_C);
            __half2 v1 = __floats2half2_rn(acc[mi][ni][2]*INV_C, acc[mi][ni][3]*INV_C);
            *(__half2*)(Cg + (size_t)r0*DI + col)     = v0;
            *(__half2*)(Cg + (size_t)(r0+8)*DI + col) = v1;
        }
}

// ---------------- Gram matrix: all 136 pairwise <G_i, G_j> per batch --------
__global__ void __launch_bounds__(128, 1) gram_k() {
    int b = blockIdx.y;
    const __half* Gb = g_G + (size_t)b*NC*NE;
    float acc[NPAIR];
#pragma unroll
    for (int p = 0; p < NPAIR; p++) acc[p] = 0.f;

    for (int e = blockIdx.x*128 + threadIdx.x; e < NE; e += gridDim.x*128) {
        float g[NC];
#pragma unroll
        for (int j = 0; j < NC; j++) g[j] = __half2float(Gb[(size_t)j*NE + e]);
        int p = 0;
#pragma unroll
        for (int j = 0; j < NC; j++)
#pragma unroll
            for (int i = 0; i <= j; i++) { acc[p] = fmaf(g[i], g[j], acc[p]); p++; }
    }
    __shared__ float sw[NPAIR*4];
    int lane = threadIdx.x & 31, w = threadIdx.x >> 5;
#pragma unroll
    for (int p = 0; p < NPAIR; p++) {
        float v = acc[p];
        v += __shfl_xor_sync(0xFFFFFFFFu, v, 16);
        v += __shfl_xor_sync(0xFFFFFFFFu, v, 8);
        v += __shfl_xor_sync(0xFFFFFFFFu, v, 4);
        v += __shfl_xor_sync(0xFFFFFFFFu, v, 2);
        v += __shfl_xor_sync(0xFFFFFFFFu, v, 1);
        if (lane == 0) sw[p*4 + w] = v;
    }
    __syncthreads();
    for (int p = threadIdx.x; p < NPAIR; p += 128)
        atomicAdd(&g_gram[b*NPAIR + p],
                  (double)(sw[p*4] + sw[p*4+1] + sw[p*4+2] + sw[p*4+3]));
}

// ---------------- scalar recursion: sA_k, sB_k from Gram --------------------
__global__ void scal2_k(const float* __restrict__ lil, const float* __restrict__ ldl) {
    int b = threadIdx.x;
    if (b >= B_) return;
    double eta   = exp((double)lil[0]);
    double sg    = 1.0/(1.0 + exp(-(double)ldl[0]));
    double decay = 0.9 + (0.995 - 0.9)*sg;
    double W0n   = sqrt(g_w0n2);
    const double* Gm = g_gram + b*NPAIR;
    double beta[NC];
#pragma unroll
    for (int j = 0; j < NC; j++) beta[j] = 0.0;
    double dwn2 = 0.0;
    for (int k = 0; k < NC; k++) {
        int rb = k*(k+1)/2;
        double gn2 = Gm[rb + k];
        double gsc = fmin(0.02*W0n/(sqrt(gn2) + 1e-8), 1.0);
        double c   = (1.0 - decay)*eta*gsc;
        double dot = 0.0;
        for (int j = 0; j < k; j++) dot += beta[j]*Gm[rb + j];
        double in2 = decay*decay*dwn2 + c*c*gn2 + 2.0*decay*c*dot;
        double s   = fmin(0.1*W0n/(sqrt(in2) + 1e-8), 1.0);
        g_sA[b*NC + k] = (float)(s*decay);
        g_sB[b*NC + k] = (float)(s*c);
        for (int j = 0; j < k; j++) beta[j] *= s*decay;
        beta[k] = s*c;
        dwn2 = in2*s*s;
    }
}

// ---------------- materialize W_k = fp16(W0 + dW_{k-1}) + deltaW ------------
__global__ void matW_k(const float* __restrict__ W0, float* __restrict__ outDW) {
    int b = blockIdx.y;
    __shared__ float sA[NC], sB[NC];
    if (threadIdx.x < NC) { sA[threadIdx.x] = g_sA[b*NC + threadIdx.x];
                            sB[threadIdx.x] = g_sB[b*NC + threadIdx.x]; }
    __syncthreads();
    for (int e = blockIdx.x*blockDim.x + threadIdx.x; e < NE; e += gridDim.x*blockDim.x) {
        float w0 = W0[e];
        float dw = 0.f;
#pragma unroll
        for (int k = 0; k < NC; k++) {
            float w = w0 + dw;
            g_Wh[((size_t)b*NC + k)*NE + e] = __float2half_rn(w);
            float g = __half2float(g_G[((size_t)b*NC + k)*NE + e]);
            dw = fmaf(sA[k], dw, sB[k]*g);
        }
        outDW[(size_t)b*NE + e] = dw;
    }
}

// ---------------- HMMA GEMM: out[t,o] = z[t,:]·W_k[o,:] + bias, split-K2 ----
__global__ void __launch_bounds__(256, 2) gemmOut_hmma(const float* __restrict__ bias,
                                                       float* __restrict__ out) {
    extern __shared__ char dsm[];
    uint32_t smb = smem_u32(dsm);
    int bz = blockIdx.z;
    int bk = bz >> 1, ks = bz & 1;          // split-K half
    int obase = blockIdx.x*128;
    int tbase = blockIdx.y*128;
    const int KH = DI/2;                     // 1024
    size_t abase = ((size_t)bk*CHK + tbase)*DI + (size_t)ks*KH;
    size_t bbase = (size_t)bk*NE + (size_t)obase*DI + (size_t)ks*KH;

    float acc[4][4][4];
#pragma unroll
    for (int i = 0; i < 4; i++)
#pragma unroll
        for (int j = 0; j < 4; j++)
#pragma unroll
            for (int r = 0; r < 4; r++) acc[i][j][r] = 0.f;

    gemm_mainloop(g_zh + abase, g_zl + abase, DI,
                  g_Wh + bbase, DI, KH, smb, acc);

    int lane = threadIdx.x & 31, wid = threadIdx.x >> 5;
    int warpM = wid >> 2, warpN = wid & 3;
    int g = lane >> 2, tc = (lane & 3)*2;
    float* dst = (ks == 0) ? out : g_part;
#pragma unroll
    for (int mi = 0; mi < 4; mi++)
#pragma unroll
        for (int ni = 0; ni < 4; ni++) {
            int r0  = tbase + warpM*64 + mi*16 + g;
            int col = obase + warpN*32 + ni*8 + tc;
            float b0 = 0.f, b1 = 0.f;
            if (ks == 0) { b0 = bias[col]; b1 = bias[col+1]; }
            float2 v0 = make_float2(acc[mi][ni][0] + b0, acc[mi][ni][1] + b1);
            float2 v1 = make_float2(acc[mi][ni][2] + b0, acc[mi][ni][3] + b1);
            *(float2*)(dst + ((size_t)bk*CHK + r0)*DM + col)     = v0;
            *(float2*)(dst + ((size_t)bk*CHK + r0 + 8)*DM + col) = v1;
        }
}

// ---------------- split-K reduce: out += g_part ------------------------------
__global__ void addpart_k(float* __restrict__ out) {
    size_t n4 = (size_t)B_*T_*DM/4;
    float4* o4 = (float4*)out;
    for (size_t i = (size_t)blockIdx.x*blockDim.x + threadIdx.x;
         i < n4; i += (size_t)gridDim.x*blockDim.x) {
        float4 a = o4[i];
        float4 p = ((const float4*)g_part)[i];
        a.x += p.x; a.y += p.y; a.z += p.z; a.w += p.w;
        o4[i] = a;
    }
}

// ---------------- launch -----------------------------------------------------
extern "C" void kernel_launch(void* const* d_in, const int* in_sizes, int n_in,
                              void* d_out, int out_size) {
    const float* z    = (const float*)d_in[0];
    const float* src  = (const float*)d_in[1];
    const float* W0   = (const float*)d_in[2];
    const float* bias = (const float*)d_in[3];
    const float* cw   = (const float*)d_in[4];
    const float* lil  = (const float*)d_in[5];
    const float* ldl  = (const float*)d_in[6];
    float* out = (float*)d_out;

    cudaFuncSetAttribute(gemmG_hmma,   cudaFuncAttributeMaxDynamicSharedMemorySize, SMEM_DYN);
    cudaFuncSetAttribute(gemmOut_hmma, cudaFuncAttributeMaxDynamicSharedMemorySize, SMEM_DYN);

    zero_scalars_k<<<2, 256>>>();
    w0norm_k<<<256, 256>>>(W0);
    conv_vu_k<<<B_*T_, 256>>>(src, cw);
    z_rms_k<<<B_*T_, 256>>>(z);
    tsplit_vu_k<<<dim3(DM/32, T_/32, B_), 256>>>();
    tsplit_zu_k<<<dim3(DI/32, T_/32, B_), 256>>>();

    gemmG_hmma<<<dim3(DI/128, DM/128, B_*NC), 256, SMEM_DYN>>>();

    gram_k<<<dim3(512, B_), 128>>>();
    scal2_k<<<1, 32>>>(lil, ldl);
    matW_k<<<dim3(1024, B_), 256>>>(W0, out + (size_t)B_*T_*DM);

    gemmOut_hmma<<<dim3(DM/128, CHK/128, B_*NC*2), 256, SMEM_DYN>>>(bias, out);
    addpart_k<<<1024, 256>>>(out);
}

// round 11
// speedup vs baseline: 2.8611x; 1.2173x over previous
#include <cuda_runtime.h>
#include <cuda_fp16.h>
#include <stdint.h>
#include <math.h>

#define B_    2
#define T_    4096
#define DM    1024
#define DI    2048
#define CHK   256
#define NC    16
#define KSZ   5
#define NE    (DM*DI)
#define NPAIR 136
#define NORM_EPS 1e-6f
#define INV_C (1.0f/256.0f)

// ---------------- scratch (device globals; no allocation allowed) ----------
__device__ float   g_vu [(size_t)B_*T_*DM];     // conv+double-rms, fp32
__device__ float   g_zu [(size_t)B_*T_*DI];     // rms(z), fp32
__device__ __half  g_G  [(size_t)B_*NC*NE];     // G_k (scaled by 1/C), fp16
__device__ float   g_part[(size_t)B_*T_*DM];    // split-K partial for out
__device__ __half  g_vuT_h[(size_t)B_*DM*T_];   // vu^T fp16 [b][o][t]
__device__ __half  g_zuT_h[(size_t)B_*DI*T_];   // zu^T fp16 [b][d][t]
__device__ __half  g_zh [(size_t)B_*T_*DI];     // z fp16 [b][t][d]
__device__ __half  g_Wh [(size_t)B_*NC*NE];     // fp16(W0+dW_{k-1}) [b][k][o][d]
__device__ double  g_gram[B_*NPAIR];
__device__ double  g_w0n2;
__device__ float   g_sA[B_*NC];
__device__ float   g_sB[B_*NC];

// ---------------- mma.sync / cp.async helpers (sm_80+, NOT arch-'a') -------
__device__ __forceinline__ uint32_t smem_u32(const void* p) {
    uint32_t a;
    asm("{ .reg .u64 t; cvta.to.shared.u64 t, %1; cvt.u32.u64 %0, t; }"
        : "=r"(a) : "l"(p));
    return a;
}
__device__ __forceinline__ void ldmx4(uint32_t r[4], uint32_t addr) {
    asm volatile("ldmatrix.sync.aligned.m8n8.x4.shared.b16 {%0,%1,%2,%3}, [%4];"
        : "=r"(r[0]), "=r"(r[1]), "=r"(r[2]), "=r"(r[3]) : "r"(addr));
}
__device__ __forceinline__ void mma16816(float c[4], const uint32_t a[4],
                                         uint32_t b0, uint32_t b1) {
    asm volatile("mma.sync.aligned.m16n8k16.row.col.f32.f16.f16.f32 "
        "{%0,%1,%2,%3}, {%4,%5,%6,%7}, {%8,%9}, {%0,%1,%2,%3};"
        : "+f"(c[0]), "+f"(c[1]), "+f"(c[2]), "+f"(c[3])
        : "r"(a[0]), "r"(a[1]), "r"(a[2]), "r"(a[3]), "r"(b0), "r"(b1));
}
#define CPASYNC16(dst, src) \
    asm volatile("cp.async.cg.shared.global [%0], [%1], 16;" :: "r"(dst), "l"(src))
#define CPCOMMIT() asm volatile("cp.async.commit_group;")
#define CPWAIT(n)  asm volatile("cp.async.wait_group %0;" :: "n"(n))

// smem: 2 operand tiles (A,B), each 128 rows x 32 fp16, row stride 80B
#define SROW   80
#define TILEB  (128*SROW)     // 10240
#define BUFB   (2*TILEB)      // 20480
#define SMEM_DYN (3*BUFB)     // 61440 (3-stage); x2 blocks = 122880

// ---------------- shared GEMM mainloop (128x128 tile, BK=32, pure fp16) -----
__device__ __forceinline__ void gemm_mainloop(
    const __half* __restrict__ A, int lda,
    const __half* __restrict__ B, int ldb,
    int K, uint32_t smb, float acc[4][4][4])
{
    int tid = threadIdx.x, lane = tid & 31, wid = tid >> 5;
    int warpM = wid >> 2, warpN = wid & 3;
    const int S = K / 32;

    int q0r = tid >> 2,          q0c = tid & 3;
    int q1r = (tid + 256) >> 2,  q1c = tid & 3;

    uint32_t aoff[4], boff[2];
#pragma unroll
    for (int mi = 0; mi < 4; mi++)
        aoff[mi] = (uint32_t)(warpM*64 + mi*16 + (lane & 15))*SROW + ((lane >> 4) & 1)*16;
#pragma unroll
    for (int bg = 0; bg < 2; bg++)
        boff[bg] = (uint32_t)(warpN*32 + bg*16 + (lane & 7) + ((lane & 16) ? 8 : 0))*SROW
                 + ((lane >> 3) & 1)*16;

    auto load_tile = [&](int s, int buf) {
        int k0 = s*32;
        uint32_t bb = smb + buf*BUFB;
        CPASYNC16(bb +           q0r*SROW + q0c*16, A + (size_t)q0r*lda + k0 + q0c*8);
        CPASYNC16(bb +           q1r*SROW + q1c*16, A + (size_t)q1r*lda + k0 + q1c*8);
        CPASYNC16(bb + TILEB +   q0r*SROW + q0c*16, B + (size_t)q0r*ldb + k0 + q0c*8);
        CPASYNC16(bb + TILEB +   q1r*SROW + q1c*16, B + (size_t)q1r*ldb + k0 + q1c*8);
        CPCOMMIT();
    };

    load_tile(0, 0);
    if (S > 1) load_tile(1, 1);

    int buf = 0;
    for (int s = 0; s < S; s++) {
        if (s < S - 1) { CPWAIT(1); }
        else           { CPWAIT(0); }
        __syncthreads();
        if (s + 2 < S) {
            int nb = buf + 2; if (nb >= 3) nb -= 3;
            load_tile(s + 2, nb);
        }
        uint32_t bb = smb + buf*BUFB;
#pragma unroll
        for (int kk = 0; kk < 2; kk++) {
            uint32_t ah[4][4], bh[2][4];
            uint32_t kb = kk*32;
#pragma unroll
            for (int mi = 0; mi < 4; mi++)
                ldmx4(ah[mi], bb +         aoff[mi] + kb);
#pragma unroll
            for (int bg = 0; bg < 2; bg++)
                ldmx4(bh[bg], bb + TILEB + boff[bg] + kb);
#pragma unroll
            for (int mi = 0; mi < 4; mi++)
#pragma unroll
                for (int ni = 0; ni < 4; ni++) {
                    int bg = ni >> 1, sub = (ni & 1)*2;
                    mma16816(acc[mi][ni], ah[mi], bh[bg][sub], bh[bg][sub+1]);
                }
        }
        buf++; if (buf >= 3) buf = 0;
    }
}

// ---------------- init ------------------------------------------------------
__global__ void zero_scalars_k() {
    int i = blockIdx.x*blockDim.x + threadIdx.x;
    if (i == 0) g_w0n2 = 0.0;
    if (i < B_*NPAIR) g_gram[i] = 0.0;
}

// ---------------- ||W0||^2 --------------------------------------------------
__global__ void w0norm_k(const float* __restrict__ W0) {
    __shared__ double sred[256];
    double s = 0.0;
    for (int i = blockIdx.x*blockDim.x + threadIdx.x; i < NE; i += gridDim.x*blockDim.x) {
        float v = W0[i];
        s += (double)v * (double)v;
    }
    sred[threadIdx.x] = s; __syncthreads();
    for (int o = 128; o > 0; o >>= 1) {
        if (threadIdx.x < o) sred[threadIdx.x] += sred[threadIdx.x + o];
        __syncthreads();
    }
    if (threadIdx.x == 0) atomicAdd(&g_w0n2, sred[0]);
}

// ---------------- causal depthwise conv + double rmsnorm -> vu (fp32) -------
__global__ void conv_vu_k(const float* __restrict__ src, const float* __restrict__ cw) {
    int bt = blockIdx.x;
    int b  = bt / T_;
    int t  = bt % T_;
    float vals[4];
    float ss = 0.f;
#pragma unroll
    for (int q = 0; q < 4; q++) {
        int o = threadIdx.x + q*256;
        float acc = 0.f;
#pragma unroll
        for (int j = 0; j < KSZ; j++) {
            int tt = t - (KSZ-1) + j;
            float x = (tt >= 0) ? src[((size_t)b*T_ + tt)*DM + o] : 0.f;
            acc = fmaf(x, cw[o*KSZ + j], acc);
        }
        vals[q] = acc;
        ss += acc*acc;
    }
    __shared__ float red[256];
    red[threadIdx.x] = ss; __syncthreads();
    for (int o = 128; o > 0; o >>= 1) {
        if (threadIdx.x < o) red[threadIdx.x] += red[threadIdx.x + o];
        __syncthreads();
    }
    float ms  = red[0] * (1.0f/DM);
    float s1  = rsqrtf(ms + NORM_EPS);
    float ms2 = ms * s1 * s1;
    float s2  = rsqrtf(ms2 + NORM_EPS);
    float s   = s1 * s2;
#pragma unroll
    for (int q = 0; q < 4; q++) {
        int o = threadIdx.x + q*256;
        g_vu[(size_t)bt*DM + o] = vals[q] * s;
    }
}

// ---------------- rmsnorm(z) -> zu (fp32) + z fp16 (fused) ------------------
__global__ void z_rms_k(const float* __restrict__ z) {
    int bt = blockIdx.x;
    const float* row = z + (size_t)bt*DI;
    float vals[8];
    float ss = 0.f;
#pragma unroll
    for (int q = 0; q < 8; q++) {
        int d = threadIdx.x + q*256;
        float v = row[d];
        vals[q] = v;
        ss += v*v;
    }
    __shared__ float red[256];
    red[threadIdx.x] = ss; __syncthreads();
    for (int o = 128; o > 0; o >>= 1) {
        if (threadIdx.x < o) red[threadIdx.x] += red[threadIdx.x + o];
        __syncthreads();
    }
    float s = rsqrtf(red[0]*(1.0f/DI) + NORM_EPS);
#pragma unroll
    for (int q = 0; q < 8; q++) {
        int d = threadIdx.x + q*256;
        float v = vals[q];
        g_zu[(size_t)bt*DI + d] = v * s;
        g_zh[(size_t)bt*DI + d] = __float2half_rn(v);
    }
}

// ---------------- transpose [b][t][W] -> [b][W][t] fp16 ---------------------
// Device globals referenced in DEVICE code only (ATS host-shadow trap).
__device__ __forceinline__ void tsplit_body(const float* __restrict__ src,
                                            __half* __restrict__ dh, int W) {
    __shared__ float tile[32][33];
    int b  = blockIdx.z;
    int w0 = blockIdx.x*32, t0 = blockIdx.y*32;
    int tid = threadIdx.x;
#pragma unroll
    for (int i = 0; i < 4; i++) {
        int q = tid + i*256; int r = q>>5, c = q&31;
        tile[r][c] = src[((size_t)b*T_ + t0 + r)*W + w0 + c];
    }
    __syncthreads();
#pragma unroll
    for (int i = 0; i < 4; i++) {
        int q = tid + i*256; int c = q>>5, r = q&31;
        size_t o = ((size_t)b*W + w0 + c)*T_ + t0 + r;
        dh[o] = __float2half_rn(tile[r][c]);
    }
}
__global__ void tsplit_vu_k() { tsplit_body(g_vu, g_vuT_h, DM); }
__global__ void tsplit_zu_k() { tsplit_body(g_zu, g_zuT_h, DI); }

// ---------------- HMMA GEMM: G[o,d] = sum_t vu[t,o] zu[t,d] / C -------------
__global__ void __launch_bounds__(256, 2) gemmG_hmma() {
    extern __shared__ char dsm[];
    uint32_t smb = smem_u32(dsm);
    int bk = blockIdx.z;
    int b = bk >> 4, kc = bk & 15;
    int obase = blockIdx.y*128;
    int dbase = blockIdx.x*128;
    size_t abase = ((size_t)b*DM + obase)*T_ + (size_t)kc*CHK;
    size_t bbase = ((size_t)b*DI + dbase)*T_ + (size_t)kc*CHK;

    float acc[4][4][4];
#pragma unroll
    for (int i = 0; i < 4; i++)
#pragma unroll
        for (int j = 0; j < 4; j++)
#pragma unroll
            for (int r = 0; r < 4; r++) acc[i][j][r] = 0.f;

    gemm_mainloop(g_vuT_h + abase, T_, g_zuT_h + bbase, T_, CHK, smb, acc);

    int lane = threadIdx.x & 31, wid = threadIdx.x >> 5;
    int warpM = wid >> 2, warpN = wid & 3;
    int g = lane >> 2, tc = (lane & 3)*2;
    __half* Cg = g_G + (size_t)bk*NE;
#pragma unroll
    for (int mi = 0; mi < 4; mi++)
#pragma unroll
        for (int ni = 0; ni < 4; ni++) {
            int r0  = obase + warpM*64 + mi*16 + g;
            int col = dbase + warpN*32 + ni*8 + tc;
            __half2 v0 = __floats2half2_rn(acc[mi][ni][0]*INV_C, acc[mi][ni][1]*INV_C);
            __half2 v1 = __floats2half2_rn(acc[mi][ni][2]*INV_C, acc[mi][ni][3]*INV_C);
            *(__half2*)(Cg + (size_t)r0*DI + col)     = v0;
            *(__half2*)(Cg + (size_t)(r0+8)*DI + col) = v1;
        }
}

// ---------------- Gram matrix: all 136 pairwise <G_i, G_j> per batch --------
__global__ void __launch_bounds__(128, 1) gram_k() {
    int b = blockIdx.y;
    const __half* Gb = g_G + (size_t)b*NC*NE;
    float acc[NPAIR];
#pragma unroll
    for (int p = 0; p < NPAIR; p++) acc[p] = 0.f;

    for (int e = blockIdx.x*128 + threadIdx.x; e < NE; e += gridDim.x*128) {
        float g[NC];
#pragma unroll
        for (int j = 0; j < NC; j++) g[j] = __half2float(Gb[(size_t)j*NE + e]);
        int p = 0;
#pragma unroll
        for (int j = 0; j < NC; j++)
#pragma unroll
            for (int i = 0; i <= j; i++) { acc[p] = fmaf(g[i], g[j], acc[p]); p++; }
    }
    __shared__ float sw[NPAIR*4];
    int lane = threadIdx.x & 31, w = threadIdx.x >> 5;
#pragma unroll
    for (int p = 0; p < NPAIR; p++) {
        float v = acc[p];
        v += __shfl_xor_sync(0xFFFFFFFFu, v, 16);
        v += __shfl_xor_sync(0xFFFFFFFFu, v, 8);
        v += __shfl_xor_sync(0xFFFFFFFFu, v, 4);
        v += __shfl_xor_sync(0xFFFFFFFFu, v, 2);
        v += __shfl_xor_sync(0xFFFFFFFFu, v, 1);
        if (lane == 0) sw[p*4 + w] = v;
    }
    __syncthreads();
    for (int p = threadIdx.x; p < NPAIR; p += 128)
        atomicAdd(&g_gram[b*NPAIR + p],
                  (double)(sw[p*4] + sw[p*4+1] + sw[p*4+2] + sw[p*4+3]));
}

// ---------------- scalar recursion: sA_k, sB_k from Gram --------------------
__global__ void scal2_k(const float* __restrict__ lil, const float* __restrict__ ldl) {
    int b = threadIdx.x;
    if (b >= B_) return;
    double eta   = exp((double)lil[0]);
    double sg    = 1.0/(1.0 + exp(-(double)ldl[0]));
    double decay = 0.9 + (0.995 - 0.9)*sg;
    double W0n   = sqrt(g_w0n2);
    const double* Gm = g_gram + b*NPAIR;
    double beta[NC];
#pragma unroll
    for (int j = 0; j < NC; j++) beta[j] = 0.0;
    double dwn2 = 0.0;
    for (int k = 0; k < NC; k++) {
        int rb = k*(k+1)/2;
        double gn2 = Gm[rb + k];
        double gsc = fmin(0.02*W0n/(sqrt(gn2) + 1e-8), 1.0);
        double c   = (1.0 - decay)*eta*gsc;
        double dot = 0.0;
        for (int j = 0; j < k; j++) dot += beta[j]*Gm[rb + j];
        double in2 = decay*decay*dwn2 + c*c*gn2 + 2.0*decay*c*dot;
        double s   = fmin(0.1*W0n/(sqrt(in2) + 1e-8), 1.0);
        g_sA[b*NC + k] = (float)(s*decay);
        g_sB[b*NC + k] = (float)(s*c);
        for (int j = 0; j < k; j++) beta[j] *= s*decay;
        beta[k] = s*c;
        dwn2 = in2*s*s;
    }
}

// ---------------- materialize W_k = fp16(W0 + dW_{k-1}) + deltaW ------------
__global__ void matW_k(const float* __restrict__ W0, float* __restrict__ outDW) {
    int b = blockIdx.y;
    __shared__ float sA[NC], sB[NC];
    if (threadIdx.x < NC) { sA[threadIdx.x] = g_sA[b*NC + threadIdx.x];
                            sB[threadIdx.x] = g_sB[b*NC + threadIdx.x]; }
    __syncthreads();
    for (int e = blockIdx.x*blockDim.x + threadIdx.x; e < NE; e += gridDim.x*blockDim.x) {
        float w0 = W0[e];
        float dw = 0.f;
#pragma unroll
        for (int k = 0; k < NC; k++) {
            float w = w0 + dw;
            g_Wh[((size_t)b*NC + k)*NE + e] = __float2half_rn(w);
            float g = __half2float(g_G[((size_t)b*NC + k)*NE + e]);
            dw = fmaf(sA[k], dw, sB[k]*g);
        }
        outDW[(size_t)b*NE + e] = dw;
    }
}

// ---------------- HMMA GEMM: out[t,o] = z[t,:]·W_k[o,:] + bias, split-K2 ----
__global__ void __launch_bounds__(256, 2) gemmOut_hmma(const float* __restrict__ bias,
                                                       float* __restrict__ out) {
    extern __shared__ char dsm[];
    uint32_t smb = smem_u32(dsm);
    int bz = blockIdx.z;
    int bk = bz >> 1, ks = bz & 1;          // split-K half
    int obase = blockIdx.x*128;
    int tbase = blockIdx.y*128;
    const int KH = DI/2;                     // 1024
    size_t abase = ((size_t)bk*CHK + tbase)*DI + (size_t)ks*KH;
    size_t bbase = (size_t)bk*NE + (size_t)obase*DI + (size_t)ks*KH;

    float acc[4][4][4];
#pragma unroll
    for (int i = 0; i < 4; i++)
#pragma unroll
        for (int j = 0; j < 4; j++)
#pragma unroll
            for (int r = 0; r < 4; r++) acc[i][j][r] = 0.f;

    gemm_mainloop(g_zh + abase, DI, g_Wh + bbase, DI, KH, smb, acc);

    int lane = threadIdx.x & 31, wid = threadIdx.x >> 5;
    int warpM = wid >> 2, warpN = wid & 3;
    int g = lane >> 2, tc = (lane & 3)*2;
    float* dst = (ks == 0) ? out : g_part;
#pragma unroll
    for (int mi = 0; mi < 4; mi++)
#pragma unroll
        for (int ni = 0; ni < 4; ni++) {
            int r0  = tbase + warpM*64 + mi*16 + g;
            int col = obase + warpN*32 + ni*8 + tc;
            float b0 = 0.f, b1 = 0.f;
            if (ks == 0) { b0 = bias[col]; b1 = bias[col+1]; }
            float2 v0 = make_float2(acc[mi][ni][0] + b0, acc[mi][ni][1] + b1);
            float2 v1 = make_float2(acc[mi][ni][2] + b0, acc[mi][ni][3] + b1);
            *(float2*)(dst + ((size_t)bk*CHK + r0)*DM + col)     = v0;
            *(float2*)(dst + ((size_t)bk*CHK + r0 + 8)*DM + col) = v1;
        }
}

// ---------------- split-K reduce: out += g_part ------------------------------
__global__ void addpart_k(float* __restrict__ out) {
    size_t n4 = (size_t)B_*T_*DM/4;
    float4* o4 = (float4*)out;
    for (size_t i = (size_t)blockIdx.x*blockDim.x + threadIdx.x;
         i < n4; i += (size_t)gridDim.x*blockDim.x) {
        float4 a = o4[i];
        float4 p = ((const float4*)g_part)[i];
        a.x += p.x; a.y += p.y; a.z += p.z; a.w += p.w;
        o4[i] = a;
    }
}

// ---------------- launch -----------------------------------------------------
extern "C" void kernel_launch(void* const* d_in, const int* in_sizes, int n_in,
                              void* d_out, int out_size) {
    const float* z    = (const float*)d_in[0];
    const float* src  = (const float*)d_in[1];
    const float* W0   = (const float*)d_in[2];
    const float* bias = (const float*)d_in[3];
    const float* cw   = (const float*)d_in[4];
    const float* lil  = (const float*)d_in[5];
    const float* ldl  = (const float*)d_in[6];
    float* out = (float*)d_out;

    cudaFuncSetAttribute(gemmG_hmma,   cudaFuncAttributeMaxDynamicSharedMemorySize, SMEM_DYN);
    cudaFuncSetAttribute(gemmOut_hmma, cudaFuncAttributeMaxDynamicSharedMemorySize, SMEM_DYN);

    zero_scalars_k<<<2, 256>>>();
    w0norm_k<<<256, 256>>>(W0);
    conv_vu_k<<<B_*T_, 256>>>(src, cw);
    z_rms_k<<<B_*T_, 256>>>(z);
    tsplit_vu_k<<<dim3(DM/32, T_/32, B_), 256>>>();
    tsplit_zu_k<<<dim3(DI/32, T_/32, B_), 256>>>();

    gemmG_hmma<<<dim3(DI/128, DM/128, B_*NC), 256, SMEM_DYN>>>();

    gram_k<<<dim3(512, B_), 128>>>();
    scal2_k<<<1, 32>>>(lil, ldl);
    matW_k<<<dim3(1024, B_), 256>>>(W0, out + (size_t)B_*T_*DM);

    gemmOut_hmma<<<dim3(DM/128, CHK/128, B_*NC*2), 256, SMEM_DYN>>>(bias, out);
    addpart_k<<<1024, 256>>>(out);
}